// round 3
// baseline (speedup 1.0000x reference)
#include <cuda_runtime.h>
#include <math.h>

#define Bv   8
#define Hv   32
#define Wv   32
#define Lv   6
#define Rv   384
#define NHv  6
#define DHv  64
#define Mv   1365
#define NEv  2304
#define HIDv 9216
#define ROWSv (Bv*Hv*Wv*Lv)     /* 49152 rows of length R */
#define BMv   (Bv*Mv)           /* 10920 unique-node rows  */
#define MLPROWS (Bv*Hv*Wv)      /* 8192 */

// ---------------- scratch (static device globals; no allocation) ----------------
__device__ float g_uniq[Bv*Mv*Rv];                 // 16 MB
__device__ float g_qb  [Bv*Mv*Rv];
__device__ float g_kb  [Bv*Mv*Rv];
__device__ float g_vb  [Bv*Mv*Rv];
__device__ float g_ob  [Bv*Mv*Rv];
__device__ float g_attn[Bv*Mv*Rv];
__device__ float g_xres[ROWSv*Rv];                 // 72 MB
__device__ float g_flat[ROWSv*Rv];                 // 72 MB (LN2 output, flattened MLP input)
__device__ float g_h1  [(size_t)MLPROWS*HIDv];     // 302 MB

__constant__ int c_off[6] = {0, 1024, 1280, 1344, 1360, 1364};

// ---------------- utility ----------------
__global__ void zero_kernel(float* p, int n) {
    int i = blockIdx.x * blockDim.x + threadIdx.x;
    int stride = gridDim.x * blockDim.x;
    for (; i < n; i += stride) p[i] = 0.f;
}

__device__ __forceinline__ float gelu_tanh(float v) {
    float u = 0.7978845608028654f * (v + 0.044715f * v * v * v);
    return 0.5f * v * (1.f + tanhf(u));
}

// ---------------- kernel 1: LN1 + segment-mean scatter into uniq ----------------
// one block (128 thr) per (b,h,w,l) row of length R=384
__global__ __launch_bounds__(128) void ln1_scatter_kernel(
    const float* __restrict__ x, const float* __restrict__ w, const float* __restrict__ bta)
{
    __shared__ float red[4];
    int row = blockIdx.x;
    int tid = threadIdx.x;
    int l = row % Lv;
    int t = row / Lv;
    int wc = t % Wv; t /= Wv;
    int hc = t % Hv;
    int b  = t / Hv;

    const float* xp = x + (size_t)row * Rv;
    float v0 = xp[tid], v1 = xp[tid + 128], v2 = xp[tid + 256];

    float s = v0 + v1 + v2;
    #pragma unroll
    for (int o = 16; o; o >>= 1) s += __shfl_down_sync(0xffffffffu, s, o);
    if ((tid & 31) == 0) red[tid >> 5] = s;
    __syncthreads();
    float mu = (red[0] + red[1] + red[2] + red[3]) * (1.f / Rv);
    __syncthreads();

    float d0 = v0 - mu, d1 = v1 - mu, d2 = v2 - mu;
    float sq = d0 * d0 + d1 * d1 + d2 * d2;
    #pragma unroll
    for (int o = 16; o; o >>= 1) sq += __shfl_down_sync(0xffffffffu, sq, o);
    if ((tid & 31) == 0) red[tid >> 5] = sq;
    __syncthreads();
    float var = (red[0] + red[1] + red[2] + red[3]) * (1.f / Rv);
    float rstd = rsqrtf(var + 1e-5f);

    int id = c_off[l] + (hc >> l) * (Wv >> l) + (wc >> l);
    float invc = 1.f / (float)(1 << (2 * l));
    float* up = g_uniq + ((size_t)b * Mv + id) * Rv;

    atomicAdd(up + tid,       (d0 * rstd * w[tid]       + bta[tid])       * invc);
    atomicAdd(up + tid + 128, (d1 * rstd * w[tid + 128] + bta[tid + 128]) * invc);
    atomicAdd(up + tid + 256, (d2 * rstd * w[tid + 256] + bta[tid + 256]) * invc);
}

// ---------------- kernel 2: tiled SGEMM  C = A(MxK) * B(KxN) + bias, epilogues ----
// EPI 0: bias. EPI 1: gelu(bias+). EPI 2: bias + residual (res same layout as C).
// Requires: K % 8 == 0, N % 128 == 0. M arbitrary (guarded).
#define BM 128
#define BN 128
#define BK 8
template<int EPI>
__global__ __launch_bounds__(256) void sgemm_kernel(
    int Mx, int Nx, int Kx,
    const float* __restrict__ A, const float* __restrict__ Bm,
    const float* __restrict__ bias, const float* __restrict__ res,
    float* __restrict__ C)
{
    __shared__ float As[BK][BM];
    __shared__ float Bs[BK][BN];
    int tid = threadIdx.x;
    int tx = tid & 15, ty = tid >> 4;
    int rowTile = blockIdx.y * BM, colTile = blockIdx.x * BN;

    int arow = tid >> 1, acol = (tid & 1) * 4;   // A: 128 rows x 8 cols, 1 float4/thr
    int brow = tid >> 5, bcol = (tid & 31) * 4;  // B: 8 rows x 128 cols, 1 float4/thr

    float acc[8][8];
    #pragma unroll
    for (int i = 0; i < 8; i++)
        #pragma unroll
        for (int j = 0; j < 8; j++) acc[i][j] = 0.f;

    for (int k0 = 0; k0 < Kx; k0 += BK) {
        int gr = rowTile + arow;
        float4 av = make_float4(0.f, 0.f, 0.f, 0.f);
        if (gr < Mx) av = *(const float4*)(A + (size_t)gr * Kx + k0 + acol);
        As[acol + 0][arow] = av.x;
        As[acol + 1][arow] = av.y;
        As[acol + 2][arow] = av.z;
        As[acol + 3][arow] = av.w;
        *(float4*)&Bs[brow][bcol] = *(const float4*)(Bm + (size_t)(k0 + brow) * Nx + colTile + bcol);
        __syncthreads();

        #pragma unroll
        for (int kk = 0; kk < BK; kk++) {
            float ar[8], br[8];
            *(float4*)&ar[0] = *(float4*)&As[kk][ty * 8];
            *(float4*)&ar[4] = *(float4*)&As[kk][ty * 8 + 4];
            *(float4*)&br[0] = *(float4*)&Bs[kk][tx * 8];
            *(float4*)&br[4] = *(float4*)&Bs[kk][tx * 8 + 4];
            #pragma unroll
            for (int i = 0; i < 8; i++)
                #pragma unroll
                for (int j = 0; j < 8; j++)
                    acc[i][j] = fmaf(ar[i], br[j], acc[i][j]);
        }
        __syncthreads();
    }

    #pragma unroll
    for (int i = 0; i < 8; i++) {
        int gr = rowTile + ty * 8 + i;
        if (gr >= Mx) continue;
        #pragma unroll
        for (int j = 0; j < 8; j++) {
            int gc = colTile + tx * 8 + j;
            float val = acc[i][j] + bias[gc];
            if (EPI == 1) val = gelu_tanh(val);
            if (EPI == 2) val += res[(size_t)gr * Nx + gc];
            C[(size_t)gr * Nx + gc] = val;
        }
    }
}

// ---------------- kernel 3: attention over M=1365 nodes, flash-style ------------
// 1 thread = 1 query row; K/V tiles of 64 keys in smem. grid (ceil(M/128), NH, B)
#define AKT 64
__global__ __launch_bounds__(128) void attn_kernel()
{
    __shared__ float Ks[AKT][DHv];
    __shared__ float Vs[AKT][DHv];
    int b = blockIdx.z, h = blockIdx.y;
    int qm = blockIdx.x * 128 + threadIdx.x;
    bool valid = qm < Mv;
    int qsafe = valid ? qm : 0;

    const float* qptr = g_qb + ((size_t)(b * Mv + qsafe)) * Rv + h * DHv;
    float q[DHv];
    #pragma unroll
    for (int d = 0; d < DHv; d += 4) {
        float4 t = *(const float4*)(qptr + d);
        q[d] = t.x; q[d + 1] = t.y; q[d + 2] = t.z; q[d + 3] = t.w;
    }
    float o[DHv];
    #pragma unroll
    for (int d = 0; d < DHv; d++) o[d] = 0.f;
    float mmax = -1e30f, lsum = 0.f;

    for (int k0 = 0; k0 < Mv; k0 += AKT) {
        int nk = min(AKT, Mv - k0);
        __syncthreads();
        for (int idx = threadIdx.x; idx < AKT * (DHv / 4); idx += 128) {
            int j = idx >> 4, dq = (idx & 15) * 4;
            if (j < nk) {
                size_t base = ((size_t)(b * Mv + k0 + j)) * Rv + h * DHv + dq;
                *(float4*)&Ks[j][dq] = *(const float4*)(g_kb + base);
                *(float4*)&Vs[j][dq] = *(const float4*)(g_vb + base);
            }
        }
        __syncthreads();
        if (valid) {
            for (int j = 0; j < nk; j++) {
                float dot = 0.f;
                #pragma unroll
                for (int d = 0; d < DHv; d++) dot = fmaf(q[d], Ks[j][d], dot);
                float s = dot * 0.125f;  // 1/sqrt(64)
                if (s <= mmax) {
                    float p = __expf(s - mmax);
                    lsum += p;
                    #pragma unroll
                    for (int d = 0; d < DHv; d++) o[d] = fmaf(p, Vs[j][d], o[d]);
                } else {
                    float alpha = __expf(mmax - s);
                    mmax = s;
                    lsum = lsum * alpha + 1.f;
                    #pragma unroll
                    for (int d = 0; d < DHv; d++) o[d] = fmaf(o[d], alpha, Vs[j][d]);
                }
            }
        }
    }
    if (valid) {
        float inv = 1.f / lsum;
        float* op = g_ob + ((size_t)(b * Mv + qm)) * Rv + h * DHv;
        #pragma unroll
        for (int d = 0; d < DHv; d += 4) {
            float4 t = make_float4(o[d] * inv, o[d + 1] * inv, o[d + 2] * inv, o[d + 3] * inv);
            *(float4*)(op + d) = t;
        }
    }
}

// ---------------- kernel 4: gather + residual + LN2 -> x_res, flat --------------
__global__ __launch_bounds__(128) void res_ln2_kernel(
    const float* __restrict__ x, const float* __restrict__ w, const float* __restrict__ bta)
{
    __shared__ float red[4];
    int row = blockIdx.x;
    int tid = threadIdx.x;
    int l = row % Lv;
    int t = row / Lv;
    int wc = t % Wv; t /= Wv;
    int hc = t % Hv;
    int b  = t / Hv;

    int id = c_off[l] + (hc >> l) * (Wv >> l) + (wc >> l);
    const float* xp = x + (size_t)row * Rv;
    const float* ap = g_attn + ((size_t)b * Mv + id) * Rv;

    float v0 = xp[tid]       + ap[tid];
    float v1 = xp[tid + 128] + ap[tid + 128];
    float v2 = xp[tid + 256] + ap[tid + 256];

    float* rp = g_xres + (size_t)row * Rv;
    rp[tid] = v0; rp[tid + 128] = v1; rp[tid + 256] = v2;

    float s = v0 + v1 + v2;
    #pragma unroll
    for (int o = 16; o; o >>= 1) s += __shfl_down_sync(0xffffffffu, s, o);
    if ((tid & 31) == 0) red[tid >> 5] = s;
    __syncthreads();
    float mu = (red[0] + red[1] + red[2] + red[3]) * (1.f / Rv);
    __syncthreads();

    float d0 = v0 - mu, d1 = v1 - mu, d2 = v2 - mu;
    float sq = d0 * d0 + d1 * d1 + d2 * d2;
    #pragma unroll
    for (int o = 16; o; o >>= 1) sq += __shfl_down_sync(0xffffffffu, sq, o);
    if ((tid & 31) == 0) red[tid >> 5] = sq;
    __syncthreads();
    float var = (red[0] + red[1] + red[2] + red[3]) * (1.f / Rv);
    float rstd = rsqrtf(var + 1e-5f);

    float* fp = g_flat + (size_t)row * Rv;  // same linearization as (B,H,W,NE)
    fp[tid]       = d0 * rstd * w[tid]       + bta[tid];
    fp[tid + 128] = d1 * rstd * w[tid + 128] + bta[tid + 128];
    fp[tid + 256] = d2 * rstd * w[tid + 256] + bta[tid + 256];
}

// ---------------- launch ----------------
extern "C" void kernel_launch(void* const* d_in, const int* in_sizes, int n_in,
                              void* d_out, int out_size) {
    const float* x    = (const float*)d_in[0];
    const float* ln1w = (const float*)d_in[1];
    const float* ln1b = (const float*)d_in[2];
    const float* ln2w = (const float*)d_in[3];
    const float* ln2b = (const float*)d_in[4];
    const float* wq = (const float*)d_in[5];  const float* bq = (const float*)d_in[6];
    const float* wk = (const float*)d_in[7];  const float* bk = (const float*)d_in[8];
    const float* wv = (const float*)d_in[9];  const float* bv = (const float*)d_in[10];
    const float* wo = (const float*)d_in[11]; const float* bo = (const float*)d_in[12];
    const float* w1 = (const float*)d_in[13]; const float* b1 = (const float*)d_in[14];
    const float* w2 = (const float*)d_in[15]; const float* b2 = (const float*)d_in[16];
    float* out = (float*)d_out;

    float *uniq, *qb, *kb, *vb, *ob, *attn, *xres, *flat, *h1;
    cudaGetSymbolAddress((void**)&uniq, g_uniq);
    cudaGetSymbolAddress((void**)&qb,   g_qb);
    cudaGetSymbolAddress((void**)&kb,   g_kb);
    cudaGetSymbolAddress((void**)&vb,   g_vb);
    cudaGetSymbolAddress((void**)&ob,   g_ob);
    cudaGetSymbolAddress((void**)&attn, g_attn);
    cudaGetSymbolAddress((void**)&xres, g_xres);
    cudaGetSymbolAddress((void**)&flat, g_flat);
    cudaGetSymbolAddress((void**)&h1,   g_h1);

    // 1. zero uniq accumulator
    zero_kernel<<<4096, 256>>>(uniq, Bv * Mv * Rv);
    // 2. LN1 + segment-mean scatter
    ln1_scatter_kernel<<<ROWSv, 128>>>(x, ln1w, ln1b);
    // 3-5. Q/K/V projections: (10920 x 384) @ (384 x 384)
    dim3 gq(Rv / BN, (BMv + BM - 1) / BM);
    sgemm_kernel<0><<<gq, 256>>>(BMv, Rv, Rv, uniq, wq, bq, nullptr, qb);
    sgemm_kernel<0><<<gq, 256>>>(BMv, Rv, Rv, uniq, wk, bk, nullptr, kb);
    sgemm_kernel<0><<<gq, 256>>>(BMv, Rv, Rv, uniq, wv, bv, nullptr, vb);
    // 6. attention over the 1365 tree nodes
    attn_kernel<<<dim3((Mv + 127) / 128, NHv, Bv), 128>>>();
    // 7. output projection
    sgemm_kernel<0><<<gq, 256>>>(BMv, Rv, Rv, ob, wo, bo, nullptr, attn);
    // 8. gather + residual + LN2
    res_ln2_kernel<<<ROWSv, 128>>>(x, ln2w, ln2b);
    // 9. MLP GEMM1 + GELU: (8192 x 2304) @ (2304 x 9216)
    sgemm_kernel<1><<<dim3(HIDv / BN, MLPROWS / BM), 256>>>(MLPROWS, HIDv, NEv, flat, w1, b1, nullptr, h1);
    // 10. MLP GEMM2 + bias + residual -> d_out: (8192 x 9216) @ (9216 x 2304)
    sgemm_kernel<2><<<dim3(NEv / BN, MLPROWS / BM), 256>>>(MLPROWS, NEv, HIDv, h1, w2, b2, xres, out);
}

// round 4
// speedup vs baseline: 3.0584x; 3.0584x over previous
#include <cuda_runtime.h>
#include <math.h>
#include <stdint.h>

#define Bv   8
#define Hv   32
#define Wv   32
#define Lv   6
#define Rv   384
#define NHv  6
#define DHv  64
#define Mv   1365
#define NEv  2304
#define HIDv 9216
#define ROWSv (Bv*Hv*Wv*Lv)     /* 49152 rows of length R */
#define BMv   (Bv*Mv)           /* 10920 unique-node rows  */
#define MLPROWS (Bv*Hv*Wv)      /* 8192 */

// ---------------- scratch (static device globals; no allocation) ----------------
__device__ float g_uniq[Bv*Mv*Rv];
__device__ float g_qb  [Bv*Mv*Rv];
__device__ float g_kb  [Bv*Mv*Rv];
__device__ float g_vb  [Bv*Mv*Rv];
__device__ float g_ob  [Bv*Mv*Rv];
__device__ float g_attn[Bv*Mv*Rv];
__device__ float g_xres[ROWSv*Rv];
__device__ float g_flat[ROWSv*Rv];
__device__ float g_h1  [(size_t)MLPROWS*HIDv];

__constant__ int c_off[6] = {0, 1024, 1280, 1344, 1360, 1364};

// ---------------- utility ----------------
__global__ void zero_kernel(float* p, int n) {
    int i = blockIdx.x * blockDim.x + threadIdx.x;
    int stride = gridDim.x * blockDim.x;
    for (; i < n; i += stride) p[i] = 0.f;
}

__device__ __forceinline__ float gelu_tanh(float v) {
    float u = 0.7978845608028654f * (v + 0.044715f * v * v * v);
    return 0.5f * v * (1.f + tanhf(u));
}

__device__ __forceinline__ uint32_t f2tf(float f) {
    uint32_t r;
    asm volatile("cvt.rna.tf32.f32 %0, %1;" : "=r"(r) : "f"(f));
    return r;
}

__device__ __forceinline__ void cp_async16(uint32_t dst, const void* src, int sz) {
    asm volatile("cp.async.cg.shared.global [%0], [%1], 16, %2;\n"
                 :: "r"(dst), "l"(src), "r"(sz));
}
__device__ __forceinline__ void cp_commit() {
    asm volatile("cp.async.commit_group;\n");
}
__device__ __forceinline__ void cp_wait_all() {
    asm volatile("cp.async.wait_group 0;\n");
}

// ---------------- kernel 1: LN1 + segment-mean scatter into uniq ----------------
__global__ __launch_bounds__(128) void ln1_scatter_kernel(
    const float* __restrict__ x, const float* __restrict__ w, const float* __restrict__ bta)
{
    __shared__ float red[4];
    int row = blockIdx.x;
    int tid = threadIdx.x;
    int l = row % Lv;
    int t = row / Lv;
    int wc = t % Wv; t /= Wv;
    int hc = t % Hv;
    int b  = t / Hv;

    const float* xp = x + (size_t)row * Rv;
    float v0 = xp[tid], v1 = xp[tid + 128], v2 = xp[tid + 256];

    float s = v0 + v1 + v2;
    #pragma unroll
    for (int o = 16; o; o >>= 1) s += __shfl_down_sync(0xffffffffu, s, o);
    if ((tid & 31) == 0) red[tid >> 5] = s;
    __syncthreads();
    float mu = (red[0] + red[1] + red[2] + red[3]) * (1.f / Rv);
    __syncthreads();

    float d0 = v0 - mu, d1 = v1 - mu, d2 = v2 - mu;
    float sq = d0 * d0 + d1 * d1 + d2 * d2;
    #pragma unroll
    for (int o = 16; o; o >>= 1) sq += __shfl_down_sync(0xffffffffu, sq, o);
    if ((tid & 31) == 0) red[tid >> 5] = sq;
    __syncthreads();
    float var = (red[0] + red[1] + red[2] + red[3]) * (1.f / Rv);
    float rstd = rsqrtf(var + 1e-5f);

    int id = c_off[l] + (hc >> l) * (Wv >> l) + (wc >> l);
    float invc = 1.f / (float)(1 << (2 * l));
    float* up = g_uniq + ((size_t)b * Mv + id) * Rv;

    atomicAdd(up + tid,       (d0 * rstd * w[tid]       + bta[tid])       * invc);
    atomicAdd(up + tid + 128, (d1 * rstd * w[tid + 128] + bta[tid + 128]) * invc);
    atomicAdd(up + tid + 256, (d2 * rstd * w[tid + 256] + bta[tid + 256]) * invc);
}

// ---------------- kernel 2: TF32 tensor-core GEMM ----------------
// C(MxN) = A(MxK) @ B(KxN) + bias, with epilogue.
// EPI 0: bias. EPI 1: gelu(bias+). EPI 2: bias + residual.
// Block tile 128x128, K-tile 32, cp.async double buffered.
// 8 warps, warp tile 64x32 (warp grid 2x4), mma.m16n8k8 tf32, 4x4 tiles per warp.
// Requires: N % 128 == 0, K % 32 == 0. M arbitrary (guarded).
#define ASTRIDE 36               /* floats per A smem row (bank-conflict-free) */
#define BSTRIDE 136              /* floats per B smem row */
#define ASZ (128*ASTRIDE)        /* 4608 floats */
#define BSZ (32*BSTRIDE)         /* 4352 floats */
#define GEMM_SMEM ((2*(ASZ+BSZ))*4)  /* 71680 bytes */

template<int EPI>
__global__ __launch_bounds__(256) void tf32_gemm_kernel(
    int Mx, int Nx, int Kx,
    const float* __restrict__ A, const float* __restrict__ Bm,
    const float* __restrict__ bias, const float* __restrict__ res,
    float* __restrict__ C)
{
    extern __shared__ float sm[];
    float* As = sm;                       // [2][ASZ]
    float* Bs = sm + 2 * ASZ;             // [2][BSZ]
    uint32_t sA = (uint32_t)__cvta_generic_to_shared(As);
    uint32_t sB = (uint32_t)__cvta_generic_to_shared(Bs);

    int tid  = threadIdx.x;
    int lane = tid & 31;
    int warp = tid >> 5;
    int wm = warp >> 2;     // 0..1
    int wn = warp & 3;      // 0..3
    int lr = lane >> 2;     // 0..7
    int lc = lane & 3;      // 0..3

    int rowTile = blockIdx.y * 128;
    int colTile = blockIdx.x * 128;

    float acc[4][4][4];
    #pragma unroll
    for (int mt = 0; mt < 4; mt++)
        #pragma unroll
        for (int nt = 0; nt < 4; nt++)
            #pragma unroll
            for (int q = 0; q < 4; q++) acc[mt][nt][q] = 0.f;

    int KT = Kx >> 5;

    // ---- tile loader (cp.async) ----
    auto load_tile = [&](int kt, int buf) {
        int k0 = kt << 5;
        #pragma unroll
        for (int i = 0; i < 4; i++) {
            int idx = i * 256 + tid;            // 0..1023
            int row = idx >> 3, c4 = (idx & 7) << 2;
            int gr = rowTile + row;
            int safe = gr < Mx ? gr : (Mx - 1);
            const float* src = A + (size_t)safe * Kx + k0 + c4;
            cp_async16(sA + (buf * ASZ + row * ASTRIDE + c4) * 4, src, gr < Mx ? 16 : 0);
        }
        #pragma unroll
        for (int i = 0; i < 4; i++) {
            int idx = i * 256 + tid;
            int row = idx >> 5, c4 = (idx & 31) << 2;
            const float* src = Bm + (size_t)(k0 + row) * Nx + colTile + c4;
            cp_async16(sB + (buf * BSZ + row * BSTRIDE + c4) * 4, src, 16);
        }
        cp_commit();
    };

    load_tile(0, 0);
    int buf = 0;

    for (int kt = 0; kt < KT; kt++) {
        cp_wait_all();
        __syncthreads();
        if (kt + 1 < KT) load_tile(kt + 1, buf ^ 1);

        const float* Ab = As + buf * ASZ;
        const float* Bb = Bs + buf * BSZ;

        #pragma unroll
        for (int kk = 0; kk < 4; kk++) {
            int k = kk << 3;
            uint32_t af[4][4];
            uint32_t bf[4][2];
            #pragma unroll
            for (int mt = 0; mt < 4; mt++) {
                int r = wm * 64 + mt * 16 + lr;
                const float* p = Ab + r * ASTRIDE + k + lc;
                af[mt][0] = f2tf(p[0]);
                af[mt][1] = f2tf(p[8 * ASTRIDE]);
                af[mt][2] = f2tf(p[4]);
                af[mt][3] = f2tf(p[8 * ASTRIDE + 4]);
            }
            #pragma unroll
            for (int nt = 0; nt < 4; nt++) {
                int c = wn * 32 + nt * 8 + lr;
                const float* p = Bb + (k + lc) * BSTRIDE + c;
                bf[nt][0] = f2tf(p[0]);
                bf[nt][1] = f2tf(p[4 * BSTRIDE]);
            }
            #pragma unroll
            for (int mt = 0; mt < 4; mt++)
                #pragma unroll
                for (int nt = 0; nt < 4; nt++) {
                    asm volatile(
                        "mma.sync.aligned.m16n8k8.row.col.f32.tf32.tf32.f32 "
                        "{%0,%1,%2,%3}, {%4,%5,%6,%7}, {%8,%9}, {%0,%1,%2,%3};\n"
                        : "+f"(acc[mt][nt][0]), "+f"(acc[mt][nt][1]),
                          "+f"(acc[mt][nt][2]), "+f"(acc[mt][nt][3])
                        : "r"(af[mt][0]), "r"(af[mt][1]), "r"(af[mt][2]), "r"(af[mt][3]),
                          "r"(bf[nt][0]), "r"(bf[nt][1]));
                }
        }
        buf ^= 1;
    }

    // ---- epilogue ----
    #pragma unroll
    for (int mt = 0; mt < 4; mt++) {
        #pragma unroll
        for (int nt = 0; nt < 4; nt++) {
            int r0 = rowTile + wm * 64 + mt * 16 + lr;
            int c0 = colTile + wn * 32 + nt * 8 + 2 * lc;
            #pragma unroll
            for (int q = 0; q < 4; q++) {
                int r = r0 + (q >> 1) * 8;
                int c = c0 + (q & 1);
                if (r < Mx) {
                    float val = acc[mt][nt][q] + bias[c];
                    if (EPI == 1) val = gelu_tanh(val);
                    if (EPI == 2) val += res[(size_t)r * Nx + c];
                    C[(size_t)r * Nx + c] = val;
                }
            }
        }
    }
}

// ---------------- kernel 3: attention over M=1365 nodes, flash-style ------------
#define AKT 64
__global__ __launch_bounds__(128) void attn_kernel()
{
    __shared__ float Ks[AKT][DHv];
    __shared__ float Vs[AKT][DHv];
    int b = blockIdx.z, h = blockIdx.y;
    int qm = blockIdx.x * 128 + threadIdx.x;
    bool valid = qm < Mv;
    int qsafe = valid ? qm : 0;

    const float* qptr = g_qb + ((size_t)(b * Mv + qsafe)) * Rv + h * DHv;
    float q[DHv];
    #pragma unroll
    for (int d = 0; d < DHv; d += 4) {
        float4 t = *(const float4*)(qptr + d);
        q[d] = t.x; q[d + 1] = t.y; q[d + 2] = t.z; q[d + 3] = t.w;
    }
    float o[DHv];
    #pragma unroll
    for (int d = 0; d < DHv; d++) o[d] = 0.f;
    float mmax = -1e30f, lsum = 0.f;

    for (int k0 = 0; k0 < Mv; k0 += AKT) {
        int nk = min(AKT, Mv - k0);
        __syncthreads();
        for (int idx = threadIdx.x; idx < AKT * (DHv / 4); idx += 128) {
            int j = idx >> 4, dq = (idx & 15) * 4;
            if (j < nk) {
                size_t base = ((size_t)(b * Mv + k0 + j)) * Rv + h * DHv + dq;
                *(float4*)&Ks[j][dq] = *(const float4*)(g_kb + base);
                *(float4*)&Vs[j][dq] = *(const float4*)(g_vb + base);
            }
        }
        __syncthreads();
        if (valid) {
            for (int j = 0; j < nk; j++) {
                float dot = 0.f;
                #pragma unroll
                for (int d = 0; d < DHv; d++) dot = fmaf(q[d], Ks[j][d], dot);
                float s = dot * 0.125f;
                if (s <= mmax) {
                    float p = __expf(s - mmax);
                    lsum += p;
                    #pragma unroll
                    for (int d = 0; d < DHv; d++) o[d] = fmaf(p, Vs[j][d], o[d]);
                } else {
                    float alpha = __expf(mmax - s);
                    mmax = s;
                    lsum = lsum * alpha + 1.f;
                    #pragma unroll
                    for (int d = 0; d < DHv; d++) o[d] = fmaf(o[d], alpha, Vs[j][d]);
                }
            }
        }
    }
    if (valid) {
        float inv = 1.f / lsum;
        float* op = g_ob + ((size_t)(b * Mv + qm)) * Rv + h * DHv;
        #pragma unroll
        for (int d = 0; d < DHv; d += 4) {
            float4 t = make_float4(o[d] * inv, o[d + 1] * inv, o[d + 2] * inv, o[d + 3] * inv);
            *(float4*)(op + d) = t;
        }
    }
}

// ---------------- kernel 4: gather + residual + LN2 -> x_res, flat --------------
__global__ __launch_bounds__(128) void res_ln2_kernel(
    const float* __restrict__ x, const float* __restrict__ w, const float* __restrict__ bta)
{
    __shared__ float red[4];
    int row = blockIdx.x;
    int tid = threadIdx.x;
    int l = row % Lv;
    int t = row / Lv;
    int wc = t % Wv; t /= Wv;
    int hc = t % Hv;
    int b  = t / Hv;

    int id = c_off[l] + (hc >> l) * (Wv >> l) + (wc >> l);
    const float* xp = x + (size_t)row * Rv;
    const float* ap = g_attn + ((size_t)b * Mv + id) * Rv;

    float v0 = xp[tid]       + ap[tid];
    float v1 = xp[tid + 128] + ap[tid + 128];
    float v2 = xp[tid + 256] + ap[tid + 256];

    float* rp = g_xres + (size_t)row * Rv;
    rp[tid] = v0; rp[tid + 128] = v1; rp[tid + 256] = v2;

    float s = v0 + v1 + v2;
    #pragma unroll
    for (int o = 16; o; o >>= 1) s += __shfl_down_sync(0xffffffffu, s, o);
    if ((tid & 31) == 0) red[tid >> 5] = s;
    __syncthreads();
    float mu = (red[0] + red[1] + red[2] + red[3]) * (1.f / Rv);
    __syncthreads();

    float d0 = v0 - mu, d1 = v1 - mu, d2 = v2 - mu;
    float sq = d0 * d0 + d1 * d1 + d2 * d2;
    #pragma unroll
    for (int o = 16; o; o >>= 1) sq += __shfl_down_sync(0xffffffffu, sq, o);
    if ((tid & 31) == 0) red[tid >> 5] = sq;
    __syncthreads();
    float var = (red[0] + red[1] + red[2] + red[3]) * (1.f / Rv);
    float rstd = rsqrtf(var + 1e-5f);

    float* fp = g_flat + (size_t)row * Rv;  // same linearization as (B,H,W,NE)
    fp[tid]       = d0 * rstd * w[tid]       + bta[tid];
    fp[tid + 128] = d1 * rstd * w[tid + 128] + bta[tid + 128];
    fp[tid + 256] = d2 * rstd * w[tid + 256] + bta[tid + 256];
}

// ---------------- launch ----------------
extern "C" void kernel_launch(void* const* d_in, const int* in_sizes, int n_in,
                              void* d_out, int out_size) {
    const float* x    = (const float*)d_in[0];
    const float* ln1w = (const float*)d_in[1];
    const float* ln1b = (const float*)d_in[2];
    const float* ln2w = (const float*)d_in[3];
    const float* ln2b = (const float*)d_in[4];
    const float* wq = (const float*)d_in[5];  const float* bq = (const float*)d_in[6];
    const float* wk = (const float*)d_in[7];  const float* bk = (const float*)d_in[8];
    const float* wv = (const float*)d_in[9];  const float* bv = (const float*)d_in[10];
    const float* wo = (const float*)d_in[11]; const float* bo = (const float*)d_in[12];
    const float* w1 = (const float*)d_in[13]; const float* b1 = (const float*)d_in[14];
    const float* w2 = (const float*)d_in[15]; const float* b2 = (const float*)d_in[16];
    float* out = (float*)d_out;

    float *uniq, *qb, *kb, *vb, *ob, *attn, *xres, *flat, *h1;
    cudaGetSymbolAddress((void**)&uniq, g_uniq);
    cudaGetSymbolAddress((void**)&qb,   g_qb);
    cudaGetSymbolAddress((void**)&kb,   g_kb);
    cudaGetSymbolAddress((void**)&vb,   g_vb);
    cudaGetSymbolAddress((void**)&ob,   g_ob);
    cudaGetSymbolAddress((void**)&attn, g_attn);
    cudaGetSymbolAddress((void**)&xres, g_xres);
    cudaGetSymbolAddress((void**)&flat, g_flat);
    cudaGetSymbolAddress((void**)&h1,   g_h1);

    static bool attr_done = false;
    if (!attr_done) {
        cudaFuncSetAttribute(tf32_gemm_kernel<0>, cudaFuncAttributeMaxDynamicSharedMemorySize, GEMM_SMEM);
        cudaFuncSetAttribute(tf32_gemm_kernel<1>, cudaFuncAttributeMaxDynamicSharedMemorySize, GEMM_SMEM);
        cudaFuncSetAttribute(tf32_gemm_kernel<2>, cudaFuncAttributeMaxDynamicSharedMemorySize, GEMM_SMEM);
        attr_done = true;
    }

    // 1. zero uniq accumulator
    zero_kernel<<<4096, 256>>>(uniq, Bv * Mv * Rv);
    // 2. LN1 + segment-mean scatter
    ln1_scatter_kernel<<<ROWSv, 128>>>(x, ln1w, ln1b);
    // 3-5. Q/K/V projections: (10920 x 384) @ (384 x 384)
    dim3 gq(Rv / 128, (BMv + 127) / 128);
    tf32_gemm_kernel<0><<<gq, 256, GEMM_SMEM>>>(BMv, Rv, Rv, uniq, wq, bq, nullptr, qb);
    tf32_gemm_kernel<0><<<gq, 256, GEMM_SMEM>>>(BMv, Rv, Rv, uniq, wk, bk, nullptr, kb);
    tf32_gemm_kernel<0><<<gq, 256, GEMM_SMEM>>>(BMv, Rv, Rv, uniq, wv, bv, nullptr, vb);
    // 6. attention over the 1365 tree nodes
    attn_kernel<<<dim3((Mv + 127) / 128, NHv, Bv), 128>>>();
    // 7. output projection
    tf32_gemm_kernel<0><<<gq, 256, GEMM_SMEM>>>(BMv, Rv, Rv, ob, wo, bo, nullptr, attn);
    // 8. gather + residual + LN2
    res_ln2_kernel<<<ROWSv, 128>>>(x, ln2w, ln2b);
    // 9. MLP GEMM1 + GELU: (8192 x 2304) @ (2304 x 9216)
    tf32_gemm_kernel<1><<<dim3(HIDv / 128, MLPROWS / 128), 256, GEMM_SMEM>>>(MLPROWS, HIDv, NEv, flat, w1, b1, nullptr, h1);
    // 10. MLP GEMM2 + bias + residual -> d_out: (8192 x 9216) @ (9216 x 2304)
    tf32_gemm_kernel<2><<<dim3(NEv / 128, MLPROWS / 128), 256, GEMM_SMEM>>>(MLPROWS, NEv, HIDv, h1, w2, b2, xres, out);
}

// round 5
// speedup vs baseline: 3.3410x; 1.0924x over previous
#include <cuda_runtime.h>
#include <math.h>
#include <stdint.h>

#define Bv   8
#define Hv   32
#define Wv   32
#define Lv   6
#define Rv   384
#define NHv  6
#define DHv  64
#define Mv   1365
#define NEv  2304
#define HIDv 9216
#define ROWSv (Bv*Hv*Wv*Lv)     /* 49152 */
#define BMv   (Bv*Mv)           /* 10920 */
#define MLPROWS (Bv*Hv*Wv)      /* 8192 */

// ---------------- scratch (static device globals; no allocation) ----------------
__device__ float g_uniq[Bv*Mv*Rv];
__device__ float g_qb  [Bv*Mv*Rv];
__device__ float g_kb  [Bv*Mv*Rv];
__device__ float g_vb  [Bv*Mv*Rv];
__device__ float g_ob  [Bv*Mv*Rv];
__device__ float g_attn[Bv*Mv*Rv];
__device__ float g_xres[ROWSv*Rv];
__device__ float g_flat[ROWSv*Rv];
__device__ float g_h1  [(size_t)MLPROWS*HIDv];
__device__ float g_w1t [(size_t)NEv*HIDv];
__device__ float g_w2t [(size_t)NEv*HIDv];
__device__ float g_wqt [Rv*Rv];
__device__ float g_wkt [Rv*Rv];
__device__ float g_wvt [Rv*Rv];
__device__ float g_wot [Rv*Rv];

__constant__ int c_off[6] = {0, 1024, 1280, 1344, 1360, 1364};

// ---------------- utility ----------------
__global__ void zero_kernel(float* p, int n) {
    int i = blockIdx.x * blockDim.x + threadIdx.x;
    int stride = gridDim.x * blockDim.x;
    for (; i < n; i += stride) p[i] = 0.f;
}

__device__ __forceinline__ float gelu_tanh(float v) {
    float u = 0.7978845608028654f * (v + 0.044715f * v * v * v);
    return 0.5f * v * (1.f + tanhf(u));
}

__device__ __forceinline__ uint32_t f2tf(float f) {
    uint32_t r;
    asm volatile("cvt.rna.tf32.f32 %0, %1;" : "=r"(r) : "f"(f));
    return r;
}
__device__ __forceinline__ float tfround(float f) { return __uint_as_float(f2tf(f)); }

__device__ __forceinline__ void cp_async16(uint32_t dst, const void* src, int sz) {
    asm volatile("cp.async.cg.shared.global [%0], [%1], 16, %2;\n"
                 :: "r"(dst), "l"(src), "r"(sz));
}
__device__ __forceinline__ void cp_commit() {
    asm volatile("cp.async.commit_group;\n");
}

// elementwise tf32 rounding (vectorized, grid-stride). n % 4 == 0.
__global__ void tf32_round_kernel(float* __restrict__ dst, const float* __restrict__ src, int n) {
    int i = (blockIdx.x * blockDim.x + threadIdx.x) * 4;
    int stride = gridDim.x * blockDim.x * 4;
    for (; i < n; i += stride) {
        float4 v = *(const float4*)(src + i);
        v.x = tfround(v.x); v.y = tfround(v.y);
        v.z = tfround(v.z); v.w = tfround(v.w);
        *(float4*)(dst + i) = v;
    }
}

// ---------------- kernel 1: LN1 + segment-mean scatter into uniq ----------------
__global__ __launch_bounds__(128) void ln1_scatter_kernel(
    const float* __restrict__ x, const float* __restrict__ w, const float* __restrict__ bta)
{
    __shared__ float red[4];
    int row = blockIdx.x;
    int tid = threadIdx.x;
    int l = row % Lv;
    int t = row / Lv;
    int wc = t % Wv; t /= Wv;
    int hc = t % Hv;
    int b  = t / Hv;

    const float* xp = x + (size_t)row * Rv;
    float v0 = xp[tid], v1 = xp[tid + 128], v2 = xp[tid + 256];

    float s = v0 + v1 + v2;
    #pragma unroll
    for (int o = 16; o; o >>= 1) s += __shfl_down_sync(0xffffffffu, s, o);
    if ((tid & 31) == 0) red[tid >> 5] = s;
    __syncthreads();
    float mu = (red[0] + red[1] + red[2] + red[3]) * (1.f / Rv);
    __syncthreads();

    float d0 = v0 - mu, d1 = v1 - mu, d2 = v2 - mu;
    float sq = d0 * d0 + d1 * d1 + d2 * d2;
    #pragma unroll
    for (int o = 16; o; o >>= 1) sq += __shfl_down_sync(0xffffffffu, sq, o);
    if ((tid & 31) == 0) red[tid >> 5] = sq;
    __syncthreads();
    float var = (red[0] + red[1] + red[2] + red[3]) * (1.f / Rv);
    float rstd = rsqrtf(var + 1e-5f);

    int id = c_off[l] + (hc >> l) * (Wv >> l) + (wc >> l);
    float invc = 1.f / (float)(1 << (2 * l));
    float* up = g_uniq + ((size_t)b * Mv + id) * Rv;

    atomicAdd(up + tid,       (d0 * rstd * w[tid]       + bta[tid])       * invc);
    atomicAdd(up + tid + 128, (d1 * rstd * w[tid + 128] + bta[tid + 128]) * invc);
    atomicAdd(up + tid + 256, (d2 * rstd * w[tid + 256] + bta[tid + 256]) * invc);
}

// ---------------- kernel 2: TF32 tensor-core GEMM (pre-rounded operands) ----------
// C(MxN) = A(MxK) @ B(KxN) + bias. A and B MUST already be tf32-rounded fp32.
// EPI 0: bias. EPI 1: gelu(bias+), output tf32-rounded. EPI 2: bias + residual.
// Block tile 256x128, K-tile 32, 3-stage cp.async pipeline.
// 8 warps, warp tile 64x64 (warp grid 4x2), mma.m16n8k8 tf32, 4x8 tiles per warp.
// Requires: N % 128 == 0, K % 32 == 0. M arbitrary (guarded).
#define BMt 256
#define BNt 128
#define ASTRIDE 36               /* floats per A smem row */
#define BSTRIDE 136              /* floats per B smem row */
#define ASZ (BMt*ASTRIDE)        /* 9216 floats */
#define BSZ (32*BSTRIDE)         /* 4352 floats */
#define NSTAGE 3
#define GEMM_SMEM (NSTAGE*(ASZ+BSZ)*4)  /* 162816 bytes */

template<int EPI>
__global__ __launch_bounds__(256, 1) void tf32_gemm_kernel(
    int Mx, int Nx, int Kx,
    const float* __restrict__ A, const float* __restrict__ Bm,
    const float* __restrict__ bias, const float* __restrict__ res,
    float* __restrict__ C)
{
    extern __shared__ float sm[];

    int tid  = threadIdx.x;
    int lane = tid & 31;
    int warp = tid >> 5;
    int wm = warp >> 1;     // 0..3
    int wn = warp & 1;      // 0..1
    int lr = lane >> 2;     // 0..7
    int lc = lane & 3;      // 0..3

    int rowTile = blockIdx.y * BMt;
    int colTile = blockIdx.x * BNt;

    float acc[4][8][4];
    #pragma unroll
    for (int mt = 0; mt < 4; mt++)
        #pragma unroll
        for (int nt = 0; nt < 8; nt++)
            #pragma unroll
            for (int q = 0; q < 4; q++) acc[mt][nt][q] = 0.f;

    int KT = Kx >> 5;

    auto load_tile = [&](int kt, int st) {
        int k0 = kt << 5;
        float* As = sm + st * (ASZ + BSZ);
        float* Bs = As + ASZ;
        uint32_t sA = (uint32_t)__cvta_generic_to_shared(As);
        uint32_t sB = (uint32_t)__cvta_generic_to_shared(Bs);
        #pragma unroll
        for (int i = 0; i < 8; i++) {
            int idx = i * 256 + tid;            // 0..2047
            int row = idx >> 3, c4 = (idx & 7) << 2;
            int gr = rowTile + row;
            const float* src = A + (size_t)(gr < Mx ? gr : (Mx - 1)) * Kx + k0 + c4;
            cp_async16(sA + (row * ASTRIDE + c4) * 4, src, gr < Mx ? 16 : 0);
        }
        #pragma unroll
        for (int i = 0; i < 4; i++) {
            int idx = i * 256 + tid;            // 0..1023
            int row = idx >> 5, c4 = (idx & 31) << 2;
            cp_async16(sB + (row * BSTRIDE + c4) * 4,
                       Bm + (size_t)(k0 + row) * Nx + colTile + c4, 16);
        }
        cp_commit();
    };

    load_tile(0, 0);
    if (KT > 1) load_tile(1, 1);

    for (int kt = 0; kt < KT; kt++) {
        if (kt + 1 < KT) asm volatile("cp.async.wait_group 1;\n");
        else             asm volatile("cp.async.wait_group 0;\n");
        __syncthreads();
        if (kt + 2 < KT) load_tile(kt + 2, (kt + 2) % NSTAGE);

        const float* Ab = sm + (kt % NSTAGE) * (ASZ + BSZ);
        const float* Bb = Ab + ASZ;

        #pragma unroll
        for (int kk = 0; kk < 4; kk++) {
            int k = kk << 3;
            uint32_t af[4][4];
            uint32_t bf[8][2];
            #pragma unroll
            for (int mt = 0; mt < 4; mt++) {
                const float* p = Ab + (wm * 64 + mt * 16 + lr) * ASTRIDE + k + lc;
                af[mt][0] = __float_as_uint(p[0]);
                af[mt][1] = __float_as_uint(p[8 * ASTRIDE]);
                af[mt][2] = __float_as_uint(p[4]);
                af[mt][3] = __float_as_uint(p[8 * ASTRIDE + 4]);
            }
            #pragma unroll
            for (int nt = 0; nt < 8; nt++) {
                const float* p = Bb + (k + lc) * BSTRIDE + wn * 64 + nt * 8 + lr;
                bf[nt][0] = __float_as_uint(p[0]);
                bf[nt][1] = __float_as_uint(p[4 * BSTRIDE]);
            }
            #pragma unroll
            for (int mt = 0; mt < 4; mt++)
                #pragma unroll
                for (int nt = 0; nt < 8; nt++) {
                    asm volatile(
                        "mma.sync.aligned.m16n8k8.row.col.f32.tf32.tf32.f32 "
                        "{%0,%1,%2,%3}, {%4,%5,%6,%7}, {%8,%9}, {%0,%1,%2,%3};\n"
                        : "+f"(acc[mt][nt][0]), "+f"(acc[mt][nt][1]),
                          "+f"(acc[mt][nt][2]), "+f"(acc[mt][nt][3])
                        : "r"(af[mt][0]), "r"(af[mt][1]), "r"(af[mt][2]), "r"(af[mt][3]),
                          "r"(bf[nt][0]), "r"(bf[nt][1]));
                }
        }
    }

    // ---- epilogue ----
    #pragma unroll
    for (int mt = 0; mt < 4; mt++) {
        #pragma unroll
        for (int nt = 0; nt < 8; nt++) {
            int r0 = rowTile + wm * 64 + mt * 16 + lr;
            int c0 = colTile + wn * 64 + nt * 8 + 2 * lc;
            #pragma unroll
            for (int q = 0; q < 4; q++) {
                int r = r0 + (q >> 1) * 8;
                int c = c0 + (q & 1);
                if (r < Mx) {
                    float val = acc[mt][nt][q] + bias[c];
                    if (EPI == 1) val = tfround(gelu_tanh(val));
                    if (EPI == 2) val += res[(size_t)r * Nx + c];
                    C[(size_t)r * Nx + c] = val;
                }
            }
        }
    }
}

// ---------------- kernel 3: attention over M=1365 nodes, flash-style ------------
#define AKT 64
__global__ __launch_bounds__(128) void attn_kernel()
{
    __shared__ float Ks[AKT][DHv];
    __shared__ float Vs[AKT][DHv];
    int b = blockIdx.z, h = blockIdx.y;
    int qm = blockIdx.x * 128 + threadIdx.x;
    bool valid = qm < Mv;
    int qsafe = valid ? qm : 0;

    const float* qptr = g_qb + ((size_t)(b * Mv + qsafe)) * Rv + h * DHv;
    float q[DHv];
    #pragma unroll
    for (int d = 0; d < DHv; d += 4) {
        float4 t = *(const float4*)(qptr + d);
        q[d] = t.x; q[d + 1] = t.y; q[d + 2] = t.z; q[d + 3] = t.w;
    }
    float o[DHv];
    #pragma unroll
    for (int d = 0; d < DHv; d++) o[d] = 0.f;
    float mmax = -1e30f, lsum = 0.f;

    for (int k0 = 0; k0 < Mv; k0 += AKT) {
        int nk = min(AKT, Mv - k0);
        __syncthreads();
        for (int idx = threadIdx.x; idx < AKT * (DHv / 4); idx += 128) {
            int j = idx >> 4, dq = (idx & 15) * 4;
            if (j < nk) {
                size_t base = ((size_t)(b * Mv + k0 + j)) * Rv + h * DHv + dq;
                *(float4*)&Ks[j][dq] = *(const float4*)(g_kb + base);
                *(float4*)&Vs[j][dq] = *(const float4*)(g_vb + base);
            }
        }
        __syncthreads();
        if (valid) {
            for (int j = 0; j < nk; j++) {
                float dot = 0.f;
                #pragma unroll
                for (int d = 0; d < DHv; d++) dot = fmaf(q[d], Ks[j][d], dot);
                float s = dot * 0.125f;
                if (s <= mmax) {
                    float p = __expf(s - mmax);
                    lsum += p;
                    #pragma unroll
                    for (int d = 0; d < DHv; d++) o[d] = fmaf(p, Vs[j][d], o[d]);
                } else {
                    float alpha = __expf(mmax - s);
                    mmax = s;
                    lsum = lsum * alpha + 1.f;
                    #pragma unroll
                    for (int d = 0; d < DHv; d++) o[d] = fmaf(o[d], alpha, Vs[j][d]);
                }
            }
        }
    }
    if (valid) {
        float inv = 1.f / lsum;
        float* op = g_ob + ((size_t)(b * Mv + qm)) * Rv + h * DHv;
        #pragma unroll
        for (int d = 0; d < DHv; d += 4) {
            // tf32-round: g_ob feeds the WO GEMM
            float4 t = make_float4(tfround(o[d] * inv), tfround(o[d + 1] * inv),
                                   tfround(o[d + 2] * inv), tfround(o[d + 3] * inv));
            *(float4*)(op + d) = t;
        }
    }
}

// ---------------- kernel 4: gather + residual + LN2 -> x_res, flat --------------
__global__ __launch_bounds__(128) void res_ln2_kernel(
    const float* __restrict__ x, const float* __restrict__ w, const float* __restrict__ bta)
{
    __shared__ float red[4];
    int row = blockIdx.x;
    int tid = threadIdx.x;
    int l = row % Lv;
    int t = row / Lv;
    int wc = t % Wv; t /= Wv;
    int hc = t % Hv;
    int b  = t / Hv;

    int id = c_off[l] + (hc >> l) * (Wv >> l) + (wc >> l);
    const float* xp = x + (size_t)row * Rv;
    const float* ap = g_attn + ((size_t)b * Mv + id) * Rv;

    float v0 = xp[tid]       + ap[tid];
    float v1 = xp[tid + 128] + ap[tid + 128];
    float v2 = xp[tid + 256] + ap[tid + 256];

    float* rp = g_xres + (size_t)row * Rv;
    rp[tid] = v0; rp[tid + 128] = v1; rp[tid + 256] = v2;

    float s = v0 + v1 + v2;
    #pragma unroll
    for (int o = 16; o; o >>= 1) s += __shfl_down_sync(0xffffffffu, s, o);
    if ((tid & 31) == 0) red[tid >> 5] = s;
    __syncthreads();
    float mu = (red[0] + red[1] + red[2] + red[3]) * (1.f / Rv);
    __syncthreads();

    float d0 = v0 - mu, d1 = v1 - mu, d2 = v2 - mu;
    float sq = d0 * d0 + d1 * d1 + d2 * d2;
    #pragma unroll
    for (int o = 16; o; o >>= 1) sq += __shfl_down_sync(0xffffffffu, sq, o);
    if ((tid & 31) == 0) red[tid >> 5] = sq;
    __syncthreads();
    float var = (red[0] + red[1] + red[2] + red[3]) * (1.f / Rv);
    float rstd = rsqrtf(var + 1e-5f);

    float* fp = g_flat + (size_t)row * Rv;  // tf32-rounded: feeds MLP GEMM1
    fp[tid]       = tfround(d0 * rstd * w[tid]       + bta[tid]);
    fp[tid + 128] = tfround(d1 * rstd * w[tid + 128] + bta[tid + 128]);
    fp[tid + 256] = tfround(d2 * rstd * w[tid + 256] + bta[tid + 256]);
}

// ---------------- launch ----------------
extern "C" void kernel_launch(void* const* d_in, const int* in_sizes, int n_in,
                              void* d_out, int out_size) {
    const float* x    = (const float*)d_in[0];
    const float* ln1w = (const float*)d_in[1];
    const float* ln1b = (const float*)d_in[2];
    const float* ln2w = (const float*)d_in[3];
    const float* ln2b = (const float*)d_in[4];
    const float* wq = (const float*)d_in[5];  const float* bq = (const float*)d_in[6];
    const float* wk = (const float*)d_in[7];  const float* bk = (const float*)d_in[8];
    const float* wv = (const float*)d_in[9];  const float* bv = (const float*)d_in[10];
    const float* wo = (const float*)d_in[11]; const float* bo = (const float*)d_in[12];
    const float* w1 = (const float*)d_in[13]; const float* b1 = (const float*)d_in[14];
    const float* w2 = (const float*)d_in[15]; const float* b2 = (const float*)d_in[16];
    float* out = (float*)d_out;

    float *uniq, *qb, *kb, *vb, *ob, *attn, *xres, *flat, *h1;
    float *w1t, *w2t, *wqt, *wkt, *wvt, *wot;
    cudaGetSymbolAddress((void**)&uniq, g_uniq);
    cudaGetSymbolAddress((void**)&qb,   g_qb);
    cudaGetSymbolAddress((void**)&kb,   g_kb);
    cudaGetSymbolAddress((void**)&vb,   g_vb);
    cudaGetSymbolAddress((void**)&ob,   g_ob);
    cudaGetSymbolAddress((void**)&attn, g_attn);
    cudaGetSymbolAddress((void**)&xres, g_xres);
    cudaGetSymbolAddress((void**)&flat, g_flat);
    cudaGetSymbolAddress((void**)&h1,   g_h1);
    cudaGetSymbolAddress((void**)&w1t,  g_w1t);
    cudaGetSymbolAddress((void**)&w2t,  g_w2t);
    cudaGetSymbolAddress((void**)&wqt,  g_wqt);
    cudaGetSymbolAddress((void**)&wkt,  g_wkt);
    cudaGetSymbolAddress((void**)&wvt,  g_wvt);
    cudaGetSymbolAddress((void**)&wot,  g_wot);

    cudaFuncSetAttribute(tf32_gemm_kernel<0>, cudaFuncAttributeMaxDynamicSharedMemorySize, GEMM_SMEM);
    cudaFuncSetAttribute(tf32_gemm_kernel<1>, cudaFuncAttributeMaxDynamicSharedMemorySize, GEMM_SMEM);
    cudaFuncSetAttribute(tf32_gemm_kernel<2>, cudaFuncAttributeMaxDynamicSharedMemorySize, GEMM_SMEM);

    // 0. tf32-round all weights into scratch copies
    tf32_round_kernel<<<2048, 256>>>(w1t, w1, NEv * HIDv);
    tf32_round_kernel<<<2048, 256>>>(w2t, w2, NEv * HIDv);
    tf32_round_kernel<<<288, 256>>>(wqt, wq, Rv * Rv);
    tf32_round_kernel<<<288, 256>>>(wkt, wk, Rv * Rv);
    tf32_round_kernel<<<288, 256>>>(wvt, wv, Rv * Rv);
    tf32_round_kernel<<<288, 256>>>(wot, wo, Rv * Rv);

    // 1. zero uniq accumulator
    zero_kernel<<<4096, 256>>>(uniq, Bv * Mv * Rv);
    // 2. LN1 + segment-mean scatter
    ln1_scatter_kernel<<<ROWSv, 128>>>(x, ln1w, ln1b);
    // 2b. round uniq in place (feeds QKV GEMMs)
    tf32_round_kernel<<<2048, 256>>>(uniq, uniq, Bv * Mv * Rv);
    // 3-5. Q/K/V projections: (10920 x 384) @ (384 x 384)
    dim3 gq(Rv / BNt, (BMv + BMt - 1) / BMt);
    tf32_gemm_kernel<0><<<gq, 256, GEMM_SMEM>>>(BMv, Rv, Rv, uniq, wqt, bq, nullptr, qb);
    tf32_gemm_kernel<0><<<gq, 256, GEMM_SMEM>>>(BMv, Rv, Rv, uniq, wkt, bk, nullptr, kb);
    tf32_gemm_kernel<0><<<gq, 256, GEMM_SMEM>>>(BMv, Rv, Rv, uniq, wvt, bv, nullptr, vb);
    // 6. attention over the 1365 tree nodes (stores tf32-rounded ob)
    attn_kernel<<<dim3((Mv + 127) / 128, NHv, Bv), 128>>>();
    // 7. output projection
    tf32_gemm_kernel<0><<<gq, 256, GEMM_SMEM>>>(BMv, Rv, Rv, ob, wot, bo, nullptr, attn);
    // 8. gather + residual + LN2 (stores tf32-rounded flat)
    res_ln2_kernel<<<ROWSv, 128>>>(x, ln2w, ln2b);
    // 9. MLP GEMM1 + GELU (rounds h1): (8192 x 2304) @ (2304 x 9216)
    tf32_gemm_kernel<1><<<dim3(HIDv / BNt, MLPROWS / BMt), 256, GEMM_SMEM>>>(MLPROWS, HIDv, NEv, flat, w1t, b1, nullptr, h1);
    // 10. MLP GEMM2 + bias + residual -> d_out: (8192 x 9216) @ (9216 x 2304)
    tf32_gemm_kernel<2><<<dim3(NEv / BNt, MLPROWS / BMt), 256, GEMM_SMEM>>>(MLPROWS, NEv, HIDv, h1, w2t, b2, xres, out);
}

// round 6
// speedup vs baseline: 3.3795x; 1.0115x over previous
#include <cuda_runtime.h>
#include <math.h>
#include <stdint.h>

#define Bv   8
#define Hv   32
#define Wv   32
#define Lv   6
#define Rv   384
#define NHv  6
#define DHv  64
#define Mv   1365
#define NEv  2304
#define HIDv 9216
#define ROWSv (Bv*Hv*Wv*Lv)     /* 49152 */
#define BMv   (Bv*Mv)           /* 10920 */
#define MLPROWS (Bv*Hv*Wv)      /* 8192 */

// ---------------- scratch (static device globals; no allocation) ----------------
__device__ float g_uniq[Bv*Mv*Rv];
__device__ float g_qb  [Bv*Mv*Rv];
__device__ float g_kb  [Bv*Mv*Rv];
__device__ float g_vb  [Bv*Mv*Rv];
__device__ float g_ob  [Bv*Mv*Rv];
__device__ float g_attn[Bv*Mv*Rv];
__device__ float g_xres[ROWSv*Rv];
__device__ float g_flat[ROWSv*Rv];
__device__ float g_h1  [(size_t)MLPROWS*HIDv];
__device__ float g_w1t [(size_t)NEv*HIDv];   // transposed [HID][NE]
__device__ float g_w2t [(size_t)NEv*HIDv];   // transposed [NE][HID]
__device__ float g_wqt [Rv*Rv];              // transposed [N][K]
__device__ float g_wkt [Rv*Rv];
__device__ float g_wvt [Rv*Rv];
__device__ float g_wot [Rv*Rv];

__constant__ int c_off[6] = {0, 1024, 1280, 1344, 1360, 1364};

// ---------------- utility ----------------
__global__ void zero_kernel(float* p, int n) {
    int i = blockIdx.x * blockDim.x + threadIdx.x;
    int stride = gridDim.x * blockDim.x;
    for (; i < n; i += stride) p[i] = 0.f;
}

__device__ __forceinline__ float gelu_tanh(float v) {
    float u = 0.7978845608028654f * (v + 0.044715f * v * v * v);
    return 0.5f * v * (1.f + tanhf(u));
}

__device__ __forceinline__ uint32_t f2tf(float f) {
    uint32_t r;
    asm volatile("cvt.rna.tf32.f32 %0, %1;" : "=r"(r) : "f"(f));
    return r;
}
__device__ __forceinline__ float tfround(float f) { return __uint_as_float(f2tf(f)); }

__device__ __forceinline__ void cp_async16(uint32_t dst, const void* src, int sz) {
    asm volatile("cp.async.cg.shared.global [%0], [%1], 16, %2;\n"
                 :: "r"(dst), "l"(src), "r"(sz));
}
__device__ __forceinline__ void cp_commit() {
    asm volatile("cp.async.commit_group;\n");
}

__device__ __forceinline__ void ldsm4(uint32_t& r0, uint32_t& r1, uint32_t& r2, uint32_t& r3,
                                      uint32_t addr) {
    asm volatile("ldmatrix.sync.aligned.m8n8.x4.shared.b16 {%0,%1,%2,%3}, [%4];"
                 : "=r"(r0), "=r"(r1), "=r"(r2), "=r"(r3) : "r"(addr));
}

// elementwise tf32 rounding (vectorized, grid-stride). n % 4 == 0.
__global__ void tf32_round_kernel(float* __restrict__ dst, const float* __restrict__ src, int n) {
    int i = (blockIdx.x * blockDim.x + threadIdx.x) * 4;
    int stride = gridDim.x * blockDim.x * 4;
    for (; i < n; i += stride) {
        float4 v = *(const float4*)(src + i);
        v.x = tfround(v.x); v.y = tfround(v.y);
        v.z = tfround(v.z); v.w = tfround(v.w);
        *(float4*)(dst + i) = v;
    }
}

// transpose + tf32 round: src[K][N] -> dst[N][K]. K,N % 32 == 0. block (32,8).
__global__ __launch_bounds__(256) void transpose_tf32_kernel(
    float* __restrict__ dst, const float* __restrict__ src, int K, int N)
{
    __shared__ float tile[32][33];
    int k0 = blockIdx.y * 32, n0 = blockIdx.x * 32;
    int tx = threadIdx.x, ty = threadIdx.y;
    #pragma unroll
    for (int i = 0; i < 32; i += 8)
        tile[ty + i][tx] = src[(size_t)(k0 + ty + i) * N + n0 + tx];
    __syncthreads();
    #pragma unroll
    for (int i = 0; i < 32; i += 8)
        dst[(size_t)(n0 + ty + i) * K + k0 + tx] = tfround(tile[tx][ty + i]);
}

// ---------------- kernel 1: LN1 + segment-mean scatter into uniq ----------------
__global__ __launch_bounds__(128) void ln1_scatter_kernel(
    const float* __restrict__ x, const float* __restrict__ w, const float* __restrict__ bta)
{
    __shared__ float red[4];
    int row = blockIdx.x;
    int tid = threadIdx.x;
    int l = row % Lv;
    int t = row / Lv;
    int wc = t % Wv; t /= Wv;
    int hc = t % Hv;
    int b  = t / Hv;

    const float* xp = x + (size_t)row * Rv;
    float v0 = xp[tid], v1 = xp[tid + 128], v2 = xp[tid + 256];

    float s = v0 + v1 + v2;
    #pragma unroll
    for (int o = 16; o; o >>= 1) s += __shfl_down_sync(0xffffffffu, s, o);
    if ((tid & 31) == 0) red[tid >> 5] = s;
    __syncthreads();
    float mu = (red[0] + red[1] + red[2] + red[3]) * (1.f / Rv);
    __syncthreads();

    float d0 = v0 - mu, d1 = v1 - mu, d2 = v2 - mu;
    float sq = d0 * d0 + d1 * d1 + d2 * d2;
    #pragma unroll
    for (int o = 16; o; o >>= 1) sq += __shfl_down_sync(0xffffffffu, sq, o);
    if ((tid & 31) == 0) red[tid >> 5] = sq;
    __syncthreads();
    float var = (red[0] + red[1] + red[2] + red[3]) * (1.f / Rv);
    float rstd = rsqrtf(var + 1e-5f);

    int id = c_off[l] + (hc >> l) * (Wv >> l) + (wc >> l);
    float invc = 1.f / (float)(1 << (2 * l));
    float* up = g_uniq + ((size_t)b * Mv + id) * Rv;

    atomicAdd(up + tid,       (d0 * rstd * w[tid]       + bta[tid])       * invc);
    atomicAdd(up + tid + 128, (d1 * rstd * w[tid + 128] + bta[tid + 128]) * invc);
    atomicAdd(up + tid + 256, (d2 * rstd * w[tid + 256] + bta[tid + 256]) * invc);
}

// ---------------- kernel 2: TF32 tensor-core GEMM (ldmatrix fragments) -----------
// C(MxN) = A(MxK) @ Bt^T + bias, where Bt is the TRANSPOSED B, layout [N][K].
// A and Bt must already be tf32-rounded fp32.
// EPI 0: bias. EPI 1: gelu(bias+), output tf32-rounded. EPI 2: bias + residual.
// Block tile 256x128, K-tile 32, 3-stage cp.async pipeline.
// 8 warps, warp tile 64x64 (warp grid 4x2), mma.m16n8k8 tf32, 4x8 tiles per warp.
// Fragments loaded via ldmatrix.x4 (A: row-major [row][k], Bt: n-major [n][k]).
// Requires: N % 128 == 0, K % 32 == 0. M arbitrary (guarded).
#define BMt 256
#define BNt 128
#define ASTRIDE 36               /* floats per A smem row  (conflict-free LDSM) */
#define BSTN    36               /* floats per Bt smem row */
#define ASZ (BMt*ASTRIDE)        /* 9216 floats */
#define BSZ (BNt*BSTN)           /* 4608 floats */
#define STG (ASZ+BSZ)            /* 13824 floats per stage */
#define NSTAGE 3
#define GEMM_SMEM (NSTAGE*STG*4) /* 165888 bytes */

template<int EPI>
__global__ __launch_bounds__(256, 1) void tf32_gemm_kernel(
    int Mx, int Nx, int Kx,
    const float* __restrict__ A, const float* __restrict__ Bt,
    const float* __restrict__ bias, const float* __restrict__ res,
    float* __restrict__ C)
{
    extern __shared__ float sm[];

    int tid  = threadIdx.x;
    int lane = tid & 31;
    int warp = tid >> 5;
    int wm = warp >> 1;     // 0..3
    int wn = warp & 1;      // 0..1
    int lr = lane >> 2;     // 0..7
    int lc = lane & 3;      // 0..3

    int rowTile = blockIdx.y * BMt;
    int colTile = blockIdx.x * BNt;

    float acc[4][8][4];
    #pragma unroll
    for (int mt = 0; mt < 4; mt++)
        #pragma unroll
        for (int nt = 0; nt < 8; nt++)
            #pragma unroll
            for (int q = 0; q < 4; q++) acc[mt][nt][q] = 0.f;

    int KT = Kx >> 5;

    auto load_tile = [&](int kt, int st) {
        int k0 = kt << 5;
        float* As = sm + st * STG;
        float* Bs = As + ASZ;
        uint32_t sA = (uint32_t)__cvta_generic_to_shared(As);
        uint32_t sB = (uint32_t)__cvta_generic_to_shared(Bs);
        #pragma unroll
        for (int i = 0; i < 8; i++) {
            int idx = i * 256 + tid;            // 2048 chunks: 256 rows x 8
            int row = idx >> 3, c4 = (idx & 7) << 2;
            int gr = rowTile + row;
            const float* src = A + (size_t)(gr < Mx ? gr : (Mx - 1)) * Kx + k0 + c4;
            cp_async16(sA + (row * ASTRIDE + c4) * 4, src, gr < Mx ? 16 : 0);
        }
        #pragma unroll
        for (int i = 0; i < 4; i++) {
            int idx = i * 256 + tid;            // 1024 chunks: 128 n-rows x 8
            int row = idx >> 3, c4 = (idx & 7) << 2;
            cp_async16(sB + (row * BSTN + c4) * 4,
                       Bt + (size_t)(colTile + row) * Kx + k0 + c4, 16);
        }
        cp_commit();
    };

    load_tile(0, 0);
    if (KT > 1) load_tile(1, 1);

    // lane-dependent LDSM address components
    uint32_t aLane = ((wm * 64 + (lane & 15)) * ASTRIDE + ((lane & 16) ? 4 : 0)) * 4;
    uint32_t bLane = ((wn * 64 + (lane & 7) + ((lane & 16) ? 8 : 0)) * BSTN
                     + ((lane & 8) ? 4 : 0)) * 4;

    for (int kt = 0; kt < KT; kt++) {
        if (kt + 1 < KT) asm volatile("cp.async.wait_group 1;\n");
        else             asm volatile("cp.async.wait_group 0;\n");
        __syncthreads();
        if (kt + 2 < KT) load_tile(kt + 2, (kt + 2) % NSTAGE);

        const float* Ab = sm + (kt % NSTAGE) * STG;
        uint32_t aBase = (uint32_t)__cvta_generic_to_shared(Ab) + aLane;
        uint32_t bBase = (uint32_t)__cvta_generic_to_shared(Ab + ASZ) + bLane;

        #pragma unroll
        for (int kk = 0; kk < 4; kk++) {
            uint32_t af[4][4];
            uint32_t bf[8][2];
            #pragma unroll
            for (int mt = 0; mt < 4; mt++)
                ldsm4(af[mt][0], af[mt][1], af[mt][2], af[mt][3],
                      aBase + (mt * 16 * ASTRIDE + kk * 8) * 4);
            #pragma unroll
            for (int np = 0; np < 4; np++)
                ldsm4(bf[2 * np][0], bf[2 * np][1], bf[2 * np + 1][0], bf[2 * np + 1][1],
                      bBase + (np * 16 * BSTN + kk * 8) * 4);
            #pragma unroll
            for (int mt = 0; mt < 4; mt++)
                #pragma unroll
                for (int nt = 0; nt < 8; nt++) {
                    asm volatile(
                        "mma.sync.aligned.m16n8k8.row.col.f32.tf32.tf32.f32 "
                        "{%0,%1,%2,%3}, {%4,%5,%6,%7}, {%8,%9}, {%0,%1,%2,%3};\n"
                        : "+f"(acc[mt][nt][0]), "+f"(acc[mt][nt][1]),
                          "+f"(acc[mt][nt][2]), "+f"(acc[mt][nt][3])
                        : "r"(af[mt][0]), "r"(af[mt][1]), "r"(af[mt][2]), "r"(af[mt][3]),
                          "r"(bf[nt][0]), "r"(bf[nt][1]));
                }
        }
    }

    // ---- epilogue ----
    #pragma unroll
    for (int mt = 0; mt < 4; mt++) {
        #pragma unroll
        for (int nt = 0; nt < 8; nt++) {
            int r0 = rowTile + wm * 64 + mt * 16 + lr;
            int c0 = colTile + wn * 64 + nt * 8 + 2 * lc;
            #pragma unroll
            for (int q = 0; q < 4; q++) {
                int r = r0 + (q >> 1) * 8;
                int c = c0 + (q & 1);
                if (r < Mx) {
                    float val = acc[mt][nt][q] + bias[c];
                    if (EPI == 1) val = tfround(gelu_tanh(val));
                    if (EPI == 2) val += res[(size_t)r * Nx + c];
                    C[(size_t)r * Nx + c] = val;
                }
            }
        }
    }
}

// ---------------- kernel 3: attention over M=1365 nodes, flash-style ------------
#define AKT 64
__global__ __launch_bounds__(128) void attn_kernel()
{
    __shared__ float Ks[AKT][DHv];
    __shared__ float Vs[AKT][DHv];
    int b = blockIdx.z, h = blockIdx.y;
    int qm = blockIdx.x * 128 + threadIdx.x;
    bool valid = qm < Mv;
    int qsafe = valid ? qm : 0;

    const float* qptr = g_qb + ((size_t)(b * Mv + qsafe)) * Rv + h * DHv;
    float q[DHv];
    #pragma unroll
    for (int d = 0; d < DHv; d += 4) {
        float4 t = *(const float4*)(qptr + d);
        q[d] = t.x; q[d + 1] = t.y; q[d + 2] = t.z; q[d + 3] = t.w;
    }
    float o[DHv];
    #pragma unroll
    for (int d = 0; d < DHv; d++) o[d] = 0.f;
    float mmax = -1e30f, lsum = 0.f;

    for (int k0 = 0; k0 < Mv; k0 += AKT) {
        int nk = min(AKT, Mv - k0);
        __syncthreads();
        for (int idx = threadIdx.x; idx < AKT * (DHv / 4); idx += 128) {
            int j = idx >> 4, dq = (idx & 15) * 4;
            if (j < nk) {
                size_t base = ((size_t)(b * Mv + k0 + j)) * Rv + h * DHv + dq;
                *(float4*)&Ks[j][dq] = *(const float4*)(g_kb + base);
                *(float4*)&Vs[j][dq] = *(const float4*)(g_vb + base);
            }
        }
        __syncthreads();
        if (valid) {
            for (int j = 0; j < nk; j++) {
                const float4* kp = (const float4*)&Ks[j][0];
                float dot = 0.f;
                #pragma unroll
                for (int d4 = 0; d4 < DHv / 4; d4++) {
                    float4 kv = kp[d4];
                    dot = fmaf(q[4 * d4],     kv.x, dot);
                    dot = fmaf(q[4 * d4 + 1], kv.y, dot);
                    dot = fmaf(q[4 * d4 + 2], kv.z, dot);
                    dot = fmaf(q[4 * d4 + 3], kv.w, dot);
                }
                float s = dot * 0.125f;
                const float4* vp = (const float4*)&Vs[j][0];
                if (s <= mmax) {
                    float p = __expf(s - mmax);
                    lsum += p;
                    #pragma unroll
                    for (int d4 = 0; d4 < DHv / 4; d4++) {
                        float4 vv = vp[d4];
                        o[4 * d4]     = fmaf(p, vv.x, o[4 * d4]);
                        o[4 * d4 + 1] = fmaf(p, vv.y, o[4 * d4 + 1]);
                        o[4 * d4 + 2] = fmaf(p, vv.z, o[4 * d4 + 2]);
                        o[4 * d4 + 3] = fmaf(p, vv.w, o[4 * d4 + 3]);
                    }
                } else {
                    float alpha = __expf(mmax - s);
                    mmax = s;
                    lsum = lsum * alpha + 1.f;
                    #pragma unroll
                    for (int d4 = 0; d4 < DHv / 4; d4++) {
                        float4 vv = vp[d4];
                        o[4 * d4]     = fmaf(o[4 * d4],     alpha, vv.x);
                        o[4 * d4 + 1] = fmaf(o[4 * d4 + 1], alpha, vv.y);
                        o[4 * d4 + 2] = fmaf(o[4 * d4 + 2], alpha, vv.z);
                        o[4 * d4 + 3] = fmaf(o[4 * d4 + 3], alpha, vv.w);
                    }
                }
            }
        }
    }
    if (valid) {
        float inv = 1.f / lsum;
        float* op = g_ob + ((size_t)(b * Mv + qm)) * Rv + h * DHv;
        #pragma unroll
        for (int d = 0; d < DHv; d += 4) {
            float4 t = make_float4(tfround(o[d] * inv), tfround(o[d + 1] * inv),
                                   tfround(o[d + 2] * inv), tfround(o[d + 3] * inv));
            *(float4*)(op + d) = t;
        }
    }
}

// ---------------- kernel 4: gather + residual + LN2 -> x_res, flat --------------
__global__ __launch_bounds__(128) void res_ln2_kernel(
    const float* __restrict__ x, const float* __restrict__ w, const float* __restrict__ bta)
{
    __shared__ float red[4];
    int row = blockIdx.x;
    int tid = threadIdx.x;
    int l = row % Lv;
    int t = row / Lv;
    int wc = t % Wv; t /= Wv;
    int hc = t % Hv;
    int b  = t / Hv;

    int id = c_off[l] + (hc >> l) * (Wv >> l) + (wc >> l);
    const float* xp = x + (size_t)row * Rv;
    const float* ap = g_attn + ((size_t)b * Mv + id) * Rv;

    float v0 = xp[tid]       + ap[tid];
    float v1 = xp[tid + 128] + ap[tid + 128];
    float v2 = xp[tid + 256] + ap[tid + 256];

    float* rp = g_xres + (size_t)row * Rv;
    rp[tid] = v0; rp[tid + 128] = v1; rp[tid + 256] = v2;

    float s = v0 + v1 + v2;
    #pragma unroll
    for (int o = 16; o; o >>= 1) s += __shfl_down_sync(0xffffffffu, s, o);
    if ((tid & 31) == 0) red[tid >> 5] = s;
    __syncthreads();
    float mu = (red[0] + red[1] + red[2] + red[3]) * (1.f / Rv);
    __syncthreads();

    float d0 = v0 - mu, d1 = v1 - mu, d2 = v2 - mu;
    float sq = d0 * d0 + d1 * d1 + d2 * d2;
    #pragma unroll
    for (int o = 16; o; o >>= 1) sq += __shfl_down_sync(0xffffffffu, sq, o);
    if ((tid & 31) == 0) red[tid >> 5] = sq;
    __syncthreads();
    float var = (red[0] + red[1] + red[2] + red[3]) * (1.f / Rv);
    float rstd = rsqrtf(var + 1e-5f);

    float* fp = g_flat + (size_t)row * Rv;  // tf32-rounded: feeds MLP GEMM1
    fp[tid]       = tfround(d0 * rstd * w[tid]       + bta[tid]);
    fp[tid + 128] = tfround(d1 * rstd * w[tid + 128] + bta[tid + 128]);
    fp[tid + 256] = tfround(d2 * rstd * w[tid + 256] + bta[tid + 256]);
}

// ---------------- launch ----------------
extern "C" void kernel_launch(void* const* d_in, const int* in_sizes, int n_in,
                              void* d_out, int out_size) {
    const float* x    = (const float*)d_in[0];
    const float* ln1w = (const float*)d_in[1];
    const float* ln1b = (const float*)d_in[2];
    const float* ln2w = (const float*)d_in[3];
    const float* ln2b = (const float*)d_in[4];
    const float* wq = (const float*)d_in[5];  const float* bq = (const float*)d_in[6];
    const float* wk = (const float*)d_in[7];  const float* bk = (const float*)d_in[8];
    const float* wv = (const float*)d_in[9];  const float* bv = (const float*)d_in[10];
    const float* wo = (const float*)d_in[11]; const float* bo = (const float*)d_in[12];
    const float* w1 = (const float*)d_in[13]; const float* b1 = (const float*)d_in[14];
    const float* w2 = (const float*)d_in[15]; const float* b2 = (const float*)d_in[16];
    float* out = (float*)d_out;

    float *uniq, *qb, *kb, *vb, *ob, *attn, *xres, *flat, *h1;
    float *w1t, *w2t, *wqt, *wkt, *wvt, *wot;
    cudaGetSymbolAddress((void**)&uniq, g_uniq);
    cudaGetSymbolAddress((void**)&qb,   g_qb);
    cudaGetSymbolAddress((void**)&kb,   g_kb);
    cudaGetSymbolAddress((void**)&vb,   g_vb);
    cudaGetSymbolAddress((void**)&ob,   g_ob);
    cudaGetSymbolAddress((void**)&attn, g_attn);
    cudaGetSymbolAddress((void**)&xres, g_xres);
    cudaGetSymbolAddress((void**)&flat, g_flat);
    cudaGetSymbolAddress((void**)&h1,   g_h1);
    cudaGetSymbolAddress((void**)&w1t,  g_w1t);
    cudaGetSymbolAddress((void**)&w2t,  g_w2t);
    cudaGetSymbolAddress((void**)&wqt,  g_wqt);
    cudaGetSymbolAddress((void**)&wkt,  g_wkt);
    cudaGetSymbolAddress((void**)&wvt,  g_wvt);
    cudaGetSymbolAddress((void**)&wot,  g_wot);

    cudaFuncSetAttribute(tf32_gemm_kernel<0>, cudaFuncAttributeMaxDynamicSharedMemorySize, GEMM_SMEM);
    cudaFuncSetAttribute(tf32_gemm_kernel<1>, cudaFuncAttributeMaxDynamicSharedMemorySize, GEMM_SMEM);
    cudaFuncSetAttribute(tf32_gemm_kernel<2>, cudaFuncAttributeMaxDynamicSharedMemorySize, GEMM_SMEM);

    // 0. transpose + tf32-round all weights into scratch copies ([N][K] layout)
    transpose_tf32_kernel<<<dim3(HIDv / 32, NEv / 32),  dim3(32, 8)>>>(w1t, w1, NEv, HIDv);
    transpose_tf32_kernel<<<dim3(NEv / 32,  HIDv / 32), dim3(32, 8)>>>(w2t, w2, HIDv, NEv);
    transpose_tf32_kernel<<<dim3(Rv / 32, Rv / 32), dim3(32, 8)>>>(wqt, wq, Rv, Rv);
    transpose_tf32_kernel<<<dim3(Rv / 32, Rv / 32), dim3(32, 8)>>>(wkt, wk, Rv, Rv);
    transpose_tf32_kernel<<<dim3(Rv / 32, Rv / 32), dim3(32, 8)>>>(wvt, wv, Rv, Rv);
    transpose_tf32_kernel<<<dim3(Rv / 32, Rv / 32), dim3(32, 8)>>>(wot, wo, Rv, Rv);

    // 1. zero uniq accumulator
    zero_kernel<<<4096, 256>>>(uniq, Bv * Mv * Rv);
    // 2. LN1 + segment-mean scatter
    ln1_scatter_kernel<<<ROWSv, 128>>>(x, ln1w, ln1b);
    // 2b. round uniq in place (feeds QKV GEMMs)
    tf32_round_kernel<<<2048, 256>>>(uniq, uniq, Bv * Mv * Rv);
    // 3-5. Q/K/V projections: (10920 x 384) @ (384 x 384)
    dim3 gq(Rv / BNt, (BMv + BMt - 1) / BMt);
    tf32_gemm_kernel<0><<<gq, 256, GEMM_SMEM>>>(BMv, Rv, Rv, uniq, wqt, bq, nullptr, qb);
    tf32_gemm_kernel<0><<<gq, 256, GEMM_SMEM>>>(BMv, Rv, Rv, uniq, wkt, bk, nullptr, kb);
    tf32_gemm_kernel<0><<<gq, 256, GEMM_SMEM>>>(BMv, Rv, Rv, uniq, wvt, bv, nullptr, vb);
    // 6. attention over the 1365 tree nodes (stores tf32-rounded ob)
    attn_kernel<<<dim3((Mv + 127) / 128, NHv, Bv), 128>>>();
    // 7. output projection
    tf32_gemm_kernel<0><<<gq, 256, GEMM_SMEM>>>(BMv, Rv, Rv, ob, wot, bo, nullptr, attn);
    // 8. gather + residual + LN2 (stores tf32-rounded flat)
    res_ln2_kernel<<<ROWSv, 128>>>(x, ln2w, ln2b);
    // 9. MLP GEMM1 + GELU (rounds h1): (8192 x 2304) @ (2304 x 9216)
    tf32_gemm_kernel<1><<<dim3(HIDv / BNt, MLPROWS / BMt), 256, GEMM_SMEM>>>(MLPROWS, HIDv, NEv, flat, w1t, b1, nullptr, h1);
    // 10. MLP GEMM2 + bias + residual -> d_out: (8192 x 9216) @ (9216 x 2304)
    tf32_gemm_kernel<2><<<dim3(NEv / BNt, MLPROWS / BMt), 256, GEMM_SMEM>>>(MLPROWS, NEv, HIDv, h1, w2t, b2, xres, out);
}

// round 7
// speedup vs baseline: 3.7316x; 1.1042x over previous
#include <cuda_runtime.h>
#include <math.h>
#include <stdint.h>

#define Bv   8
#define Hv   32
#define Wv   32
#define Lv   6
#define Rv   384
#define NHv  6
#define DHv  64
#define Mv   1365
#define NEv  2304
#define HIDv 9216
#define ROWSv (Bv*Hv*Wv*Lv)     /* 49152 */
#define BMv   (Bv*Mv)           /* 10920 */
#define MLPROWS (Bv*Hv*Wv)      /* 8192 */

// ---------------- scratch (static device globals; no allocation) ----------------
__device__ float g_uniq[Bv*Mv*Rv];
__device__ float g_qb  [Bv*Mv*Rv];
__device__ float g_kb  [Bv*Mv*Rv];
__device__ float g_vb  [Bv*Mv*Rv];
__device__ float g_ob  [Bv*Mv*Rv];
__device__ float g_attn[Bv*Mv*Rv];
__device__ float g_xres[ROWSv*Rv];
__device__ float g_flat[ROWSv*Rv];
__device__ float g_h1  [(size_t)MLPROWS*HIDv];
__device__ float g_w1t [(size_t)NEv*HIDv];   // transposed [HID][NE]
__device__ float g_w2t [(size_t)NEv*HIDv];   // transposed [NE][HID]
__device__ float g_wqt [Rv*Rv];              // transposed [N][K]
__device__ float g_wkt [Rv*Rv];
__device__ float g_wvt [Rv*Rv];
__device__ float g_wot [Rv*Rv];

__constant__ int c_off[6] = {0, 1024, 1280, 1344, 1360, 1364};

// ---------------- utility ----------------
__global__ void zero_kernel(float* p, int n) {
    int i = blockIdx.x * blockDim.x + threadIdx.x;
    int stride = gridDim.x * blockDim.x;
    for (; i < n; i += stride) p[i] = 0.f;
}

__device__ __forceinline__ float gelu_tanh(float v) {
    float u = 0.7978845608028654f * (v + 0.044715f * v * v * v);
    return 0.5f * v * (1.f + tanhf(u));
}

__device__ __forceinline__ uint32_t f2tf(float f) {
    uint32_t r;
    asm volatile("cvt.rna.tf32.f32 %0, %1;" : "=r"(r) : "f"(f));
    return r;
}
__device__ __forceinline__ float tfround(float f) { return __uint_as_float(f2tf(f)); }

__device__ __forceinline__ void cp_async16(uint32_t dst, const void* src, int sz) {
    asm volatile("cp.async.cg.shared.global [%0], [%1], 16, %2;\n"
                 :: "r"(dst), "l"(src), "r"(sz));
}
__device__ __forceinline__ void cp_commit() {
    asm volatile("cp.async.commit_group;\n");
}

__device__ __forceinline__ void ldsm4(uint32_t& r0, uint32_t& r1, uint32_t& r2, uint32_t& r3,
                                      uint32_t addr) {
    asm volatile("ldmatrix.sync.aligned.m8n8.x4.shared.b16 {%0,%1,%2,%3}, [%4];"
                 : "=r"(r0), "=r"(r1), "=r"(r2), "=r"(r3) : "r"(addr));
}

// elementwise tf32 rounding (vectorized, grid-stride). n % 4 == 0.
__global__ void tf32_round_kernel(float* __restrict__ dst, const float* __restrict__ src, int n) {
    int i = (blockIdx.x * blockDim.x + threadIdx.x) * 4;
    int stride = gridDim.x * blockDim.x * 4;
    for (; i < n; i += stride) {
        float4 v = *(const float4*)(src + i);
        v.x = tfround(v.x); v.y = tfround(v.y);
        v.z = tfround(v.z); v.w = tfround(v.w);
        *(float4*)(dst + i) = v;
    }
}

// transpose + tf32 round: src[K][N] -> dst[N][K]. K,N % 32 == 0. block (32,8).
__global__ __launch_bounds__(256) void transpose_tf32_kernel(
    float* __restrict__ dst, const float* __restrict__ src, int K, int N)
{
    __shared__ float tile[32][33];
    int k0 = blockIdx.y * 32, n0 = blockIdx.x * 32;
    int tx = threadIdx.x, ty = threadIdx.y;
    #pragma unroll
    for (int i = 0; i < 32; i += 8)
        tile[ty + i][tx] = src[(size_t)(k0 + ty + i) * N + n0 + tx];
    __syncthreads();
    #pragma unroll
    for (int i = 0; i < 32; i += 8)
        dst[(size_t)(n0 + ty + i) * K + k0 + tx] = tfround(tile[tx][ty + i]);
}

// ---------------- kernel 1: LN1 + segment-mean scatter into uniq ----------------
__global__ __launch_bounds__(128) void ln1_scatter_kernel(
    const float* __restrict__ x, const float* __restrict__ w, const float* __restrict__ bta)
{
    __shared__ float red[4];
    int row = blockIdx.x;
    int tid = threadIdx.x;
    int l = row % Lv;
    int t = row / Lv;
    int wc = t % Wv; t /= Wv;
    int hc = t % Hv;
    int b  = t / Hv;

    const float* xp = x + (size_t)row * Rv;
    float v0 = xp[tid], v1 = xp[tid + 128], v2 = xp[tid + 256];

    float s = v0 + v1 + v2;
    #pragma unroll
    for (int o = 16; o; o >>= 1) s += __shfl_down_sync(0xffffffffu, s, o);
    if ((tid & 31) == 0) red[tid >> 5] = s;
    __syncthreads();
    float mu = (red[0] + red[1] + red[2] + red[3]) * (1.f / Rv);
    __syncthreads();

    float d0 = v0 - mu, d1 = v1 - mu, d2 = v2 - mu;
    float sq = d0 * d0 + d1 * d1 + d2 * d2;
    #pragma unroll
    for (int o = 16; o; o >>= 1) sq += __shfl_down_sync(0xffffffffu, sq, o);
    if ((tid & 31) == 0) red[tid >> 5] = sq;
    __syncthreads();
    float var = (red[0] + red[1] + red[2] + red[3]) * (1.f / Rv);
    float rstd = rsqrtf(var + 1e-5f);

    int id = c_off[l] + (hc >> l) * (Wv >> l) + (wc >> l);
    float invc = 1.f / (float)(1 << (2 * l));
    float* up = g_uniq + ((size_t)b * Mv + id) * Rv;

    atomicAdd(up + tid,       (d0 * rstd * w[tid]       + bta[tid])       * invc);
    atomicAdd(up + tid + 128, (d1 * rstd * w[tid + 128] + bta[tid + 128]) * invc);
    atomicAdd(up + tid + 256, (d2 * rstd * w[tid + 256] + bta[tid + 256]) * invc);
}

// ---------------- kernel 2: TF32 tensor-core GEMM (ldmatrix, 2 CTAs/SM) ----------
// C(MxN) = A(MxK) @ Bt^T + bias, Bt layout [N][K], operands pre-rounded tf32.
// EPI 0: bias. EPI 1: gelu(bias+), tf32-rounded out. EPI 2: bias + residual.
// Block tile 128x128, K-tile 32, 3-stage cp.async. smem 110.6KB -> 2 CTAs/SM.
// 8 warps, warp tile 64x32 (grid 2x4), mma.m16n8k8 tf32, 4x4 tiles/warp (64 acc regs).
// Requires: N % 128 == 0, K % 32 == 0. M arbitrary (guarded).
#define BMt 128
#define BNt 128
#define ASTRIDE 36               /* floats per A smem row (conflict-free LDSM) */
#define BSTN    36               /* floats per Bt smem row */
#define ASZ (BMt*ASTRIDE)        /* 4608 floats */
#define BSZ (BNt*BSTN)           /* 4608 floats */
#define STG (ASZ+BSZ)            /* 9216 floats per stage */
#define NSTAGE 3
#define GEMM_SMEM (NSTAGE*STG*4) /* 110592 bytes */

template<int EPI>
__global__ __launch_bounds__(256, 2) void tf32_gemm_kernel(
    int Mx, int Nx, int Kx,
    const float* __restrict__ A, const float* __restrict__ Bt,
    const float* __restrict__ bias, const float* __restrict__ res,
    float* __restrict__ C)
{
    extern __shared__ float sm[];

    int tid  = threadIdx.x;
    int lane = tid & 31;
    int warp = tid >> 5;
    int wm = warp >> 2;     // 0..1
    int wn = warp & 3;      // 0..3
    int lr = lane >> 2;     // 0..7
    int lc = lane & 3;      // 0..3

    int rowTile = blockIdx.y * BMt;
    int colTile = blockIdx.x * BNt;

    float acc[4][4][4];
    #pragma unroll
    for (int mt = 0; mt < 4; mt++)
        #pragma unroll
        for (int nt = 0; nt < 4; nt++)
            #pragma unroll
            for (int q = 0; q < 4; q++) acc[mt][nt][q] = 0.f;

    int KT = Kx >> 5;

    auto load_tile = [&](int kt, int st) {
        int k0 = kt << 5;
        float* As = sm + st * STG;
        float* Bs = As + ASZ;
        uint32_t sA = (uint32_t)__cvta_generic_to_shared(As);
        uint32_t sB = (uint32_t)__cvta_generic_to_shared(Bs);
        #pragma unroll
        for (int i = 0; i < 4; i++) {
            int idx = i * 256 + tid;            // 1024 chunks: 128 rows x 8
            int row = idx >> 3, c4 = (idx & 7) << 2;
            int gr = rowTile + row;
            const float* src = A + (size_t)(gr < Mx ? gr : (Mx - 1)) * Kx + k0 + c4;
            cp_async16(sA + (row * ASTRIDE + c4) * 4, src, gr < Mx ? 16 : 0);
        }
        #pragma unroll
        for (int i = 0; i < 4; i++) {
            int idx = i * 256 + tid;            // 1024 chunks: 128 n-rows x 8
            int row = idx >> 3, c4 = (idx & 7) << 2;
            cp_async16(sB + (row * BSTN + c4) * 4,
                       Bt + (size_t)(colTile + row) * Kx + k0 + c4, 16);
        }
        cp_commit();
    };

    load_tile(0, 0);
    if (KT > 1) load_tile(1, 1);

    // lane-dependent LDSM address components
    uint32_t aLane = ((wm * 64 + (lane & 15)) * ASTRIDE + ((lane & 16) ? 4 : 0)) * 4;
    uint32_t bLane = ((wn * 32 + (lane & 7) + ((lane & 16) ? 8 : 0)) * BSTN
                     + ((lane & 8) ? 4 : 0)) * 4;

    for (int kt = 0; kt < KT; kt++) {
        if (kt + 1 < KT) asm volatile("cp.async.wait_group 1;\n");
        else             asm volatile("cp.async.wait_group 0;\n");
        __syncthreads();
        if (kt + 2 < KT) load_tile(kt + 2, (kt + 2) % NSTAGE);

        const float* Ab = sm + (kt % NSTAGE) * STG;
        uint32_t aBase = (uint32_t)__cvta_generic_to_shared(Ab) + aLane;
        uint32_t bBase = (uint32_t)__cvta_generic_to_shared(Ab + ASZ) + bLane;

        #pragma unroll
        for (int kk = 0; kk < 4; kk++) {
            uint32_t af[4][4];
            uint32_t bf[4][2];
            #pragma unroll
            for (int mt = 0; mt < 4; mt++)
                ldsm4(af[mt][0], af[mt][1], af[mt][2], af[mt][3],
                      aBase + (mt * 16 * ASTRIDE + kk * 8) * 4);
            #pragma unroll
            for (int np = 0; np < 2; np++)
                ldsm4(bf[2 * np][0], bf[2 * np][1], bf[2 * np + 1][0], bf[2 * np + 1][1],
                      bBase + (np * 16 * BSTN + kk * 8) * 4);
            #pragma unroll
            for (int mt = 0; mt < 4; mt++)
                #pragma unroll
                for (int nt = 0; nt < 4; nt++) {
                    asm volatile(
                        "mma.sync.aligned.m16n8k8.row.col.f32.tf32.tf32.f32 "
                        "{%0,%1,%2,%3}, {%4,%5,%6,%7}, {%8,%9}, {%0,%1,%2,%3};\n"
                        : "+f"(acc[mt][nt][0]), "+f"(acc[mt][nt][1]),
                          "+f"(acc[mt][nt][2]), "+f"(acc[mt][nt][3])
                        : "r"(af[mt][0]), "r"(af[mt][1]), "r"(af[mt][2]), "r"(af[mt][3]),
                          "r"(bf[nt][0]), "r"(bf[nt][1]));
                }
        }
    }

    // ---- epilogue ----
    #pragma unroll
    for (int mt = 0; mt < 4; mt++) {
        #pragma unroll
        for (int nt = 0; nt < 4; nt++) {
            int r0 = rowTile + wm * 64 + mt * 16 + lr;
            int c0 = colTile + wn * 32 + nt * 8 + 2 * lc;
            #pragma unroll
            for (int q = 0; q < 4; q++) {
                int r = r0 + (q >> 1) * 8;
                int c = c0 + (q & 1);
                if (r < Mx) {
                    float val = acc[mt][nt][q] + bias[c];
                    if (EPI == 1) val = tfround(gelu_tanh(val));
                    if (EPI == 2) val += res[(size_t)r * Nx + c];
                    C[(size_t)r * Nx + c] = val;
                }
            }
        }
    }
}

// ---------------- kernel 3: attention over M=1365 nodes, flash-style ------------
#define AKT 64
__global__ __launch_bounds__(128) void attn_kernel()
{
    __shared__ float Ks[AKT][DHv];
    __shared__ float Vs[AKT][DHv];
    int b = blockIdx.z, h = blockIdx.y;
    int qm = blockIdx.x * 128 + threadIdx.x;
    bool valid = qm < Mv;
    int qsafe = valid ? qm : 0;

    const float* qptr = g_qb + ((size_t)(b * Mv + qsafe)) * Rv + h * DHv;
    float q[DHv];
    #pragma unroll
    for (int d = 0; d < DHv; d += 4) {
        float4 t = *(const float4*)(qptr + d);
        q[d] = t.x; q[d + 1] = t.y; q[d + 2] = t.z; q[d + 3] = t.w;
    }
    float o[DHv];
    #pragma unroll
    for (int d = 0; d < DHv; d++) o[d] = 0.f;
    float mmax = -1e30f, lsum = 0.f;

    for (int k0 = 0; k0 < Mv; k0 += AKT) {
        int nk = min(AKT, Mv - k0);
        __syncthreads();
        for (int idx = threadIdx.x; idx < AKT * (DHv / 4); idx += 128) {
            int j = idx >> 4, dq = (idx & 15) * 4;
            if (j < nk) {
                size_t base = ((size_t)(b * Mv + k0 + j)) * Rv + h * DHv + dq;
                *(float4*)&Ks[j][dq] = *(const float4*)(g_kb + base);
                *(float4*)&Vs[j][dq] = *(const float4*)(g_vb + base);
            }
        }
        __syncthreads();
        if (valid) {
            for (int j = 0; j < nk; j++) {
                const float4* kp = (const float4*)&Ks[j][0];
                float dot = 0.f;
                #pragma unroll
                for (int d4 = 0; d4 < DHv / 4; d4++) {
                    float4 kv = kp[d4];
                    dot = fmaf(q[4 * d4],     kv.x, dot);
                    dot = fmaf(q[4 * d4 + 1], kv.y, dot);
                    dot = fmaf(q[4 * d4 + 2], kv.z, dot);
                    dot = fmaf(q[4 * d4 + 3], kv.w, dot);
                }
                float s = dot * 0.125f;
                const float4* vp = (const float4*)&Vs[j][0];
                if (s <= mmax) {
                    float p = __expf(s - mmax);
                    lsum += p;
                    #pragma unroll
                    for (int d4 = 0; d4 < DHv / 4; d4++) {
                        float4 vv = vp[d4];
                        o[4 * d4]     = fmaf(p, vv.x, o[4 * d4]);
                        o[4 * d4 + 1] = fmaf(p, vv.y, o[4 * d4 + 1]);
                        o[4 * d4 + 2] = fmaf(p, vv.z, o[4 * d4 + 2]);
                        o[4 * d4 + 3] = fmaf(p, vv.w, o[4 * d4 + 3]);
                    }
                } else {
                    float alpha = __expf(mmax - s);
                    mmax = s;
                    lsum = lsum * alpha + 1.f;
                    #pragma unroll
                    for (int d4 = 0; d4 < DHv / 4; d4++) {
                        float4 vv = vp[d4];
                        o[4 * d4]     = fmaf(o[4 * d4],     alpha, vv.x);
                        o[4 * d4 + 1] = fmaf(o[4 * d4 + 1], alpha, vv.y);
                        o[4 * d4 + 2] = fmaf(o[4 * d4 + 2], alpha, vv.z);
                        o[4 * d4 + 3] = fmaf(o[4 * d4 + 3], alpha, vv.w);
                    }
                }
            }
        }
    }
    if (valid) {
        float inv = 1.f / lsum;
        float* op = g_ob + ((size_t)(b * Mv + qm)) * Rv + h * DHv;
        #pragma unroll
        for (int d = 0; d < DHv; d += 4) {
            float4 t = make_float4(tfround(o[d] * inv), tfround(o[d + 1] * inv),
                                   tfround(o[d + 2] * inv), tfround(o[d + 3] * inv));
            *(float4*)(op + d) = t;
        }
    }
}

// ---------------- kernel 4: gather + residual + LN2 -> x_res, flat --------------
__global__ __launch_bounds__(128) void res_ln2_kernel(
    const float* __restrict__ x, const float* __restrict__ w, const float* __restrict__ bta)
{
    __shared__ float red[4];
    int row = blockIdx.x;
    int tid = threadIdx.x;
    int l = row % Lv;
    int t = row / Lv;
    int wc = t % Wv; t /= Wv;
    int hc = t % Hv;
    int b  = t / Hv;

    int id = c_off[l] + (hc >> l) * (Wv >> l) + (wc >> l);
    const float* xp = x + (size_t)row * Rv;
    const float* ap = g_attn + ((size_t)b * Mv + id) * Rv;

    float v0 = xp[tid]       + ap[tid];
    float v1 = xp[tid + 128] + ap[tid + 128];
    float v2 = xp[tid + 256] + ap[tid + 256];

    float* rp = g_xres + (size_t)row * Rv;
    rp[tid] = v0; rp[tid + 128] = v1; rp[tid + 256] = v2;

    float s = v0 + v1 + v2;
    #pragma unroll
    for (int o = 16; o; o >>= 1) s += __shfl_down_sync(0xffffffffu, s, o);
    if ((tid & 31) == 0) red[tid >> 5] = s;
    __syncthreads();
    float mu = (red[0] + red[1] + red[2] + red[3]) * (1.f / Rv);
    __syncthreads();

    float d0 = v0 - mu, d1 = v1 - mu, d2 = v2 - mu;
    float sq = d0 * d0 + d1 * d1 + d2 * d2;
    #pragma unroll
    for (int o = 16; o; o >>= 1) sq += __shfl_down_sync(0xffffffffu, sq, o);
    if ((tid & 31) == 0) red[tid >> 5] = sq;
    __syncthreads();
    float var = (red[0] + red[1] + red[2] + red[3]) * (1.f / Rv);
    float rstd = rsqrtf(var + 1e-5f);

    float* fp = g_flat + (size_t)row * Rv;  // tf32-rounded: feeds MLP GEMM1
    fp[tid]       = tfround(d0 * rstd * w[tid]       + bta[tid]);
    fp[tid + 128] = tfround(d1 * rstd * w[tid + 128] + bta[tid + 128]);
    fp[tid + 256] = tfround(d2 * rstd * w[tid + 256] + bta[tid + 256]);
}

// ---------------- launch ----------------
extern "C" void kernel_launch(void* const* d_in, const int* in_sizes, int n_in,
                              void* d_out, int out_size) {
    const float* x    = (const float*)d_in[0];
    const float* ln1w = (const float*)d_in[1];
    const float* ln1b = (const float*)d_in[2];
    const float* ln2w = (const float*)d_in[3];
    const float* ln2b = (const float*)d_in[4];
    const float* wq = (const float*)d_in[5];  const float* bq = (const float*)d_in[6];
    const float* wk = (const float*)d_in[7];  const float* bk = (const float*)d_in[8];
    const float* wv = (const float*)d_in[9];  const float* bv = (const float*)d_in[10];
    const float* wo = (const float*)d_in[11]; const float* bo = (const float*)d_in[12];
    const float* w1 = (const float*)d_in[13]; const float* b1 = (const float*)d_in[14];
    const float* w2 = (const float*)d_in[15]; const float* b2 = (const float*)d_in[16];
    float* out = (float*)d_out;

    float *uniq, *qb, *kb, *vb, *ob, *attn, *xres, *flat, *h1;
    float *w1t, *w2t, *wqt, *wkt, *wvt, *wot;
    cudaGetSymbolAddress((void**)&uniq, g_uniq);
    cudaGetSymbolAddress((void**)&qb,   g_qb);
    cudaGetSymbolAddress((void**)&kb,   g_kb);
    cudaGetSymbolAddress((void**)&vb,   g_vb);
    cudaGetSymbolAddress((void**)&ob,   g_ob);
    cudaGetSymbolAddress((void**)&attn, g_attn);
    cudaGetSymbolAddress((void**)&xres, g_xres);
    cudaGetSymbolAddress((void**)&flat, g_flat);
    cudaGetSymbolAddress((void**)&h1,   g_h1);
    cudaGetSymbolAddress((void**)&w1t,  g_w1t);
    cudaGetSymbolAddress((void**)&w2t,  g_w2t);
    cudaGetSymbolAddress((void**)&wqt,  g_wqt);
    cudaGetSymbolAddress((void**)&wkt,  g_wkt);
    cudaGetSymbolAddress((void**)&wvt,  g_wvt);
    cudaGetSymbolAddress((void**)&wot,  g_wot);

    cudaFuncSetAttribute(tf32_gemm_kernel<0>, cudaFuncAttributeMaxDynamicSharedMemorySize, GEMM_SMEM);
    cudaFuncSetAttribute(tf32_gemm_kernel<1>, cudaFuncAttributeMaxDynamicSharedMemorySize, GEMM_SMEM);
    cudaFuncSetAttribute(tf32_gemm_kernel<2>, cudaFuncAttributeMaxDynamicSharedMemorySize, GEMM_SMEM);

    // 0. transpose + tf32-round all weights into scratch copies ([N][K] layout)
    transpose_tf32_kernel<<<dim3(HIDv / 32, NEv / 32),  dim3(32, 8)>>>(w1t, w1, NEv, HIDv);
    transpose_tf32_kernel<<<dim3(NEv / 32,  HIDv / 32), dim3(32, 8)>>>(w2t, w2, HIDv, NEv);
    transpose_tf32_kernel<<<dim3(Rv / 32, Rv / 32), dim3(32, 8)>>>(wqt, wq, Rv, Rv);
    transpose_tf32_kernel<<<dim3(Rv / 32, Rv / 32), dim3(32, 8)>>>(wkt, wk, Rv, Rv);
    transpose_tf32_kernel<<<dim3(Rv / 32, Rv / 32), dim3(32, 8)>>>(wvt, wv, Rv, Rv);
    transpose_tf32_kernel<<<dim3(Rv / 32, Rv / 32), dim3(32, 8)>>>(wot, wo, Rv, Rv);

    // 1. zero uniq accumulator
    zero_kernel<<<4096, 256>>>(uniq, Bv * Mv * Rv);
    // 2. LN1 + segment-mean scatter
    ln1_scatter_kernel<<<ROWSv, 128>>>(x, ln1w, ln1b);
    // 2b. round uniq in place (feeds QKV GEMMs)
    tf32_round_kernel<<<2048, 256>>>(uniq, uniq, Bv * Mv * Rv);
    // 3-5. Q/K/V projections: (10920 x 384) @ (384 x 384)
    dim3 gq(Rv / BNt, (BMv + BMt - 1) / BMt);
    tf32_gemm_kernel<0><<<gq, 256, GEMM_SMEM>>>(BMv, Rv, Rv, uniq, wqt, bq, nullptr, qb);
    tf32_gemm_kernel<0><<<gq, 256, GEMM_SMEM>>>(BMv, Rv, Rv, uniq, wkt, bk, nullptr, kb);
    tf32_gemm_kernel<0><<<gq, 256, GEMM_SMEM>>>(BMv, Rv, Rv, uniq, wvt, bv, nullptr, vb);
    // 6. attention over the 1365 tree nodes (stores tf32-rounded ob)
    attn_kernel<<<dim3((Mv + 127) / 128, NHv, Bv), 128>>>();
    // 7. output projection
    tf32_gemm_kernel<0><<<gq, 256, GEMM_SMEM>>>(BMv, Rv, Rv, ob, wot, bo, nullptr, attn);
    // 8. gather + residual + LN2 (stores tf32-rounded flat)
    res_ln2_kernel<<<ROWSv, 128>>>(x, ln2w, ln2b);
    // 9. MLP GEMM1 + GELU (rounds h1): (8192 x 2304) @ (2304 x 9216)
    tf32_gemm_kernel<1><<<dim3(HIDv / BNt, MLPROWS / BMt), 256, GEMM_SMEM>>>(MLPROWS, HIDv, NEv, flat, w1t, b1, nullptr, h1);
    // 10. MLP GEMM2 + bias + residual -> d_out: (8192 x 9216) @ (9216 x 2304)
    tf32_gemm_kernel<2><<<dim3(NEv / BNt, MLPROWS / BMt), 256, GEMM_SMEM>>>(MLPROWS, NEv, HIDv, h1, w2t, b2, xres, out);
}